// round 5
// baseline (speedup 1.0000x reference)
#include <cuda_runtime.h>
#include <math.h>
#include <stdint.h>

#define TT 2048
#define CC 1024
#define HH 16
#define DD 64
#define BBATCH 2
#define MTOT (BBATCH * TT)   // 4096
#define FFDIM (4 * CC)       // 4096

// -------- scratch (alloc-free) --------
__device__ float g_h1[MTOT * CC];
__device__ float g_q[MTOT * CC];     // (b,h,t,d)
__device__ float g_k[MTOT * CC];
__device__ float g_v[MTOT * CC];
__device__ float g_attn[MTOT * CC];
__device__ float g_x1[MTOT * CC];
__device__ float g_h2[MTOT * CC];
__device__ float g_ff1[MTOT * FFDIM];
// tf32-rounded weight copies
__device__ float g_rwq[HH * CC * DD];
__device__ float g_rwk[HH * CC * DD];
__device__ float g_rwv[HH * CC * DD];
__device__ float g_rwp[CC * CC];
__device__ float g_rw1[CC * FFDIM];
__device__ float g_rw2[FFDIM * CC];

// -------- helpers --------
__device__ __forceinline__ unsigned f2tf(float f) {
    unsigned u;
    asm("cvt.rna.tf32.f32 %0, %1;" : "=r"(u) : "f"(f));
    return u;
}
__device__ __forceinline__ float f2tff(float f) { return __uint_as_float(f2tf(f)); }
__device__ __forceinline__ void mma_tf32(float* c, const unsigned* a, const unsigned* b) {
    asm volatile(
        "mma.sync.aligned.m16n8k8.row.col.f32.tf32.tf32.f32 "
        "{%0,%1,%2,%3}, {%4,%5,%6,%7}, {%8,%9}, {%0,%1,%2,%3};"
        : "+f"(c[0]), "+f"(c[1]), "+f"(c[2]), "+f"(c[3])
        : "r"(a[0]), "r"(a[1]), "r"(a[2]), "r"(a[3]), "r"(b[0]), "r"(b[1]));
}
__device__ __forceinline__ void cp16(uint32_t s, const void* g) {
    asm volatile("cp.async.ca.shared.global [%0], [%1], 16;" :: "r"(s), "l"(g));
}
__device__ __forceinline__ void cp_commit() { asm volatile("cp.async.commit_group;"); }
template <int N>
__device__ __forceinline__ void cp_wait() { asm volatile("cp.async.wait_group %0;" :: "n"(N)); }
__device__ __forceinline__ void ldsm4(unsigned& r0, unsigned& r1, unsigned& r2, unsigned& r3,
                                      uint32_t a) {
    asm volatile("ldmatrix.sync.aligned.m8n8.x4.shared.b16 {%0,%1,%2,%3}, [%4];"
                 : "=r"(r0), "=r"(r1), "=r"(r2), "=r"(r3) : "r"(a));
}

// ============================================================
// Weight pre-round (fp32 -> tf32 RNA), elementwise
// ============================================================
__global__ void round_w(const float* __restrict__ src, float* __restrict__ dst, int n) {
    for (int i = (blockIdx.x * 256 + threadIdx.x) * 4; i < n; i += gridDim.x * 256 * 4) {
        float4 v = *(const float4*)(src + i);
        float4 o = {f2tff(v.x), f2tff(v.y), f2tff(v.z), f2tff(v.w)};
        *(float4*)(dst + i) = o;
    }
}

// ============================================================
// LayerNorm: one block (256 thr) per row of 1024; tf32-rounded out
// ============================================================
__global__ void ln_kernel(const float* __restrict__ x, const float* __restrict__ g,
                          const float* __restrict__ b, float* __restrict__ out) {
    __shared__ float red[8];
    __shared__ float s_mu, s_rstd;
    int row = blockIdx.x;
    int tid = threadIdx.x;
    const float* xr = x + (size_t)row * CC;

    float v0 = xr[tid], v1 = xr[tid + 256], v2 = xr[tid + 512], v3 = xr[tid + 768];
    float s = v0 + v1 + v2 + v3;
    #pragma unroll
    for (int o = 16; o > 0; o >>= 1) s += __shfl_xor_sync(0xffffffffu, s, o);
    if ((tid & 31) == 0) red[tid >> 5] = s;
    __syncthreads();
    if (tid == 0) {
        float t = 0.f;
        #pragma unroll
        for (int i = 0; i < 8; i++) t += red[i];
        s_mu = t * (1.0f / CC);
    }
    __syncthreads();
    float mu = s_mu;
    float d0 = v0 - mu, d1 = v1 - mu, d2 = v2 - mu, d3 = v3 - mu;
    float s2 = d0 * d0 + d1 * d1 + d2 * d2 + d3 * d3;
    #pragma unroll
    for (int o = 16; o > 0; o >>= 1) s2 += __shfl_xor_sync(0xffffffffu, s2, o);
    __syncthreads();
    if ((tid & 31) == 0) red[tid >> 5] = s2;
    __syncthreads();
    if (tid == 0) {
        float t = 0.f;
        #pragma unroll
        for (int i = 0; i < 8; i++) t += red[i];
        s_rstd = rsqrtf(t * (1.0f / CC) + 1e-5f);
    }
    __syncthreads();
    float rstd = s_rstd;
    float* orow = out + (size_t)row * CC;
    orow[tid]       = f2tff(d0 * rstd * g[tid]       + b[tid]);
    orow[tid + 256] = f2tff(d1 * rstd * g[tid + 256] + b[tid + 256]);
    orow[tid + 512] = f2tff(d2 * rstd * g[tid + 512] + b[tid + 512]);
    orow[tid + 768] = f2tff(d3 * rstd * g[tid + 768] + b[tid + 768]);
}

// ============================================================
// tf32 GEMM, cp.async 3-stage, ldmatrix A-frags, 1 sync/iter.
// BM=128, BN=128, BK=32, 256 thr = 8 warps (2x4), warp tile 64x32.
// Dynamic smem: 3*(128*36 + 32*136)*4 = 107520 B.
// ============================================================
#define G_ASTG (128 * 36)
#define G_BSTG (32 * 136)
#define G_SMEM ((3 * (G_ASTG + G_BSTG)) * 4)

template <bool RELU, bool ROUNDOUT>
__global__ __launch_bounds__(256, 2) void gemm_mma(
    const float* __restrict__ A, const float* __restrict__ Bm,
    const float* __restrict__ bias, const float* __restrict__ res,
    float* __restrict__ C, int M, int N, int K) {
    extern __shared__ float smx[];
    float* Bsm = smx + 3 * G_ASTG;
    uint32_t sA = (uint32_t)__cvta_generic_to_shared(smx);
    uint32_t sB = (uint32_t)__cvta_generic_to_shared(Bsm);

    int tid = threadIdx.x;
    int warp = tid >> 5, lane = tid & 31;
    int g = lane >> 2, t = lane & 3;
    int tile = lane >> 3, rl = lane & 7;
    int wm = (warp >> 2) * 64, wn = (warp & 3) * 32;
    int m0 = blockIdx.y * 128, n0 = blockIdx.x * 128;

    float acc[4][4][4] = {};
    int a_rbase = wm + (tile & 1) * 8 + rl;
    int a_sbase = (tile >> 1);

    auto pre = [&](int st, int k0) {
        #pragma unroll
        for (int i = 0; i < 4; i++) {
            int ch = tid + 256 * i;
            int r = ch >> 3, sg = ch & 7;
            cp16(sA + (uint32_t)(st * G_ASTG + r * 36 + sg * 4) * 4,
                 A + (size_t)(m0 + r) * K + k0 + sg * 4);
        }
        #pragma unroll
        for (int i = 0; i < 4; i++) {
            int ch = tid + 256 * i;
            int r = ch >> 5, c = (ch & 31) * 4;
            cp16(sB + (uint32_t)(st * G_BSTG + r * 136 + c) * 4,
                 Bm + (size_t)(k0 + r) * N + n0 + c);
        }
        cp_commit();
    };

    pre(0, 0);
    pre(1, 32);
    int nk = K >> 5;
    int st = 0;
    for (int kk = 0; kk < nk; kk++) {
        if (kk + 1 < nk) cp_wait<1>(); else cp_wait<0>();
        __syncthreads();
        if (kk + 2 < nk) {
            int stp = st + 2; if (stp >= 3) stp -= 3;
            pre(stp, (kk + 2) << 5);
        }

        const float* bsp = Bsm + st * G_BSTG;
        uint32_t sAs = sA + (uint32_t)(st * G_ASTG) * 4;
        #pragma unroll
        for (int ks = 0; ks < 4; ks++) {
            unsigned af[4][4];
            #pragma unroll
            for (int mi = 0; mi < 4; mi++) {
                ldsm4(af[mi][0], af[mi][1], af[mi][2], af[mi][3],
                      sAs + (uint32_t)((a_rbase + mi * 16) * 36 + (2 * ks + a_sbase) * 4) * 4);
            }
            #pragma unroll
            for (int nj = 0; nj < 4; nj++) {
                unsigned bf[2];
                bf[0] = __float_as_uint(bsp[(ks * 8 + t) * 136 + wn + nj * 8 + g]);
                bf[1] = __float_as_uint(bsp[(ks * 8 + t + 4) * 136 + wn + nj * 8 + g]);
                #pragma unroll
                for (int mi = 0; mi < 4; mi++) mma_tf32(acc[mi][nj], af[mi], bf);
            }
        }
        if (++st == 3) st = 0;
    }

    #pragma unroll
    for (int mi = 0; mi < 4; mi++) {
        #pragma unroll
        for (int nj = 0; nj < 4; nj++) {
            int c = n0 + wn + nj * 8 + 2 * t;
            int r0 = m0 + wm + mi * 16 + g;
            int r1 = r0 + 8;
            float2 o0 = {acc[mi][nj][0], acc[mi][nj][1]};
            float2 o1 = {acc[mi][nj][2], acc[mi][nj][3]};
            if (bias) {
                float2 bv = *(const float2*)(bias + c);
                o0.x += bv.x; o0.y += bv.y; o1.x += bv.x; o1.y += bv.y;
            }
            if (res) {
                float2 ra = *(const float2*)(res + (size_t)r0 * N + c);
                float2 rb = *(const float2*)(res + (size_t)r1 * N + c);
                o0.x += ra.x; o0.y += ra.y; o1.x += rb.x; o1.y += rb.y;
            }
            if (RELU) {
                o0.x = fmaxf(o0.x, 0.f); o0.y = fmaxf(o0.y, 0.f);
                o1.x = fmaxf(o1.x, 0.f); o1.y = fmaxf(o1.y, 0.f);
            }
            if (ROUNDOUT) {
                o0.x = f2tff(o0.x); o0.y = f2tff(o0.y);
                o1.x = f2tff(o1.x); o1.y = f2tff(o1.y);
            }
            *(float2*)(C + (size_t)r0 * N + c) = o0;
            *(float2*)(C + (size_t)r1 * N + c) = o1;
        }
    }
}

// ============================================================
// QKV GEMM: BM=128, BN=64, BK=32, 128 thr, 3-stage.
// Dynamic smem: 3*(128*36 + 32*72)*4 = 82944 B. out (b,h,t,d), tf32-rounded.
// ============================================================
#define Q_ASTG (128 * 36)
#define Q_BSTG (32 * 72)
#define Q_SMEM ((3 * (Q_ASTG + Q_BSTG)) * 4)

__global__ __launch_bounds__(128) void qkv_mma(
    const float* __restrict__ h, const float* __restrict__ wq,
    const float* __restrict__ wk, const float* __restrict__ wv,
    float* __restrict__ q, float* __restrict__ k, float* __restrict__ v) {
    extern __shared__ float smx[];
    float* Bsm = smx + 3 * Q_ASTG;
    uint32_t sA = (uint32_t)__cvta_generic_to_shared(smx);
    uint32_t sB = (uint32_t)__cvta_generic_to_shared(Bsm);

    int which = blockIdx.y / HH, head = blockIdx.y % HH;
    const float* W = (which == 0 ? wq : (which == 1 ? wk : wv)) + (size_t)head * CC * DD;
    float* O = (which == 0 ? q : (which == 1 ? k : v));

    int tid = threadIdx.x;
    int warp = tid >> 5, lane = tid & 31;
    int g = lane >> 2, t = lane & 3;
    int tile = lane >> 3, rl = lane & 7;
    int wm = (warp >> 1) * 64, wn = (warp & 1) * 32;
    int m0 = blockIdx.x * 128;

    float acc[4][4][4] = {};
    int a_rbase = wm + (tile & 1) * 8 + rl;
    int a_sbase = (tile >> 1);

    auto pre = [&](int st, int k0) {
        #pragma unroll
        for (int i = 0; i < 8; i++) {
            int ch = tid + 128 * i;
            int r = ch >> 3, sg = ch & 7;
            cp16(sA + (uint32_t)(st * Q_ASTG + r * 36 + sg * 4) * 4,
                 h + (size_t)(m0 + r) * CC + k0 + sg * 4);
        }
        #pragma unroll
        for (int i = 0; i < 4; i++) {
            int ch = tid + 128 * i;
            int r = ch >> 4, c = (ch & 15) * 4;
            cp16(sB + (uint32_t)(st * Q_BSTG + r * 72 + c) * 4,
                 W + (size_t)(k0 + r) * DD + c);
        }
        cp_commit();
    };

    pre(0, 0);
    pre(1, 32);
    int nk = CC >> 5;
    int st = 0;
    for (int kk = 0; kk < nk; kk++) {
        if (kk + 1 < nk) cp_wait<1>(); else cp_wait<0>();
        __syncthreads();
        if (kk + 2 < nk) {
            int stp = st + 2; if (stp >= 3) stp -= 3;
            pre(stp, (kk + 2) << 5);
        }

        const float* bsp = Bsm + st * Q_BSTG;
        uint32_t sAs = sA + (uint32_t)(st * Q_ASTG) * 4;
        #pragma unroll
        for (int ks = 0; ks < 4; ks++) {
            unsigned af[4][4];
            #pragma unroll
            for (int mi = 0; mi < 4; mi++) {
                ldsm4(af[mi][0], af[mi][1], af[mi][2], af[mi][3],
                      sAs + (uint32_t)((a_rbase + mi * 16) * 36 + (2 * ks + a_sbase) * 4) * 4);
            }
            #pragma unroll
            for (int nj = 0; nj < 4; nj++) {
                unsigned bf[2];
                bf[0] = __float_as_uint(bsp[(ks * 8 + t) * 72 + wn + nj * 8 + g]);
                bf[1] = __float_as_uint(bsp[(ks * 8 + t + 4) * 72 + wn + nj * 8 + g]);
                #pragma unroll
                for (int mi = 0; mi < 4; mi++) mma_tf32(acc[mi][nj], af[mi], bf);
            }
        }
        if (++st == 3) st = 0;
    }

    #pragma unroll
    for (int mi = 0; mi < 4; mi++) {
        #pragma unroll
        for (int nj = 0; nj < 4; nj++) {
            int c = wn + nj * 8 + 2 * t;
            int m0r = m0 + wm + mi * 16 + g;
            int m1r = m0r + 8;
            int b0 = m0r >> 11, t0i = m0r & (TT - 1);
            int b1 = m1r >> 11, t1i = m1r & (TT - 1);
            float2 o0 = {f2tff(acc[mi][nj][0]), f2tff(acc[mi][nj][1])};
            float2 o1 = {f2tff(acc[mi][nj][2]), f2tff(acc[mi][nj][3])};
            *(float2*)(O + (((size_t)(b0 * HH + head) * TT + t0i) << 6) + c) = o0;
            *(float2*)(O + (((size_t)(b1 * HH + head) * TT + t1i) << 6) + c) = o1;
        }
    }
}

// ============================================================
// Flash attention. Br=128, Bc=64, 256 thr (8 warps).
// P in its own smem buffer (warp-local store->ldsm, __syncwarp only).
// K via cp.async; V transposed+swizzled; 2 syncthreads per tile.
// ============================================================
#define ATT_SMEM ((128 * 68 + 2 * 64 * 68) * 4)   // 69632 B

__global__ __launch_bounds__(256) void attn_mma(
    const float* __restrict__ Q, const float* __restrict__ K,
    const float* __restrict__ V, float* __restrict__ out) {
    extern __shared__ float smx[];
    float* Ps  = smx;                        // 128x68: Q staging, then P
    float* Ksm = smx + 128 * 68;             // 64x68 K tile (key-major)
    float* Vtm = smx + 128 * 68 + 64 * 68;   // 64x68 V^T [d][key], swizzled
    uint32_t sP = (uint32_t)__cvta_generic_to_shared(Ps);
    uint32_t sK = (uint32_t)__cvta_generic_to_shared(Ksm);
    uint32_t sV = (uint32_t)__cvta_generic_to_shared(Vtm);

    int bh = blockIdx.y;
    int t0 = blockIdx.x * 128;
    const float* Qp = Q + (size_t)bh * TT * DD;
    const float* Kp = K + (size_t)bh * TT * DD;
    const float* Vp = V + (size_t)bh * TT * DD;

    int tid = threadIdx.x;
    int warp = tid >> 5, lane = tid & 31;
    int g = lane >> 2, t = lane & 3;
    int tile = lane >> 3, rl = lane & 7;
    int wr = warp * 16;

    // stage Q (scaled; q already tf32, *0.125 exact) into Ps
    #pragma unroll
    for (int i = 0; i < 8; i++) {
        int idx = tid + 256 * i;
        int r = idx >> 4, c4 = (idx & 15) * 4;
        float4 qv = *(const float4*)(Qp + (size_t)(t0 + r) * DD + c4);
        float4 o = {qv.x * 0.125f, qv.y * 0.125f, qv.z * 0.125f, qv.w * 0.125f};
        *(float4*)&Ps[r * 68 + c4] = o;
    }
    __syncthreads();
    unsigned qa[8][4];
    {
        int row = wr + (tile & 1) * 8 + rl;
        #pragma unroll
        for (int ks = 0; ks < 8; ks++)
            ldsm4(qa[ks][0], qa[ks][1], qa[ks][2], qa[ks][3],
                  sP + (uint32_t)(row * 68 + (2 * ks + (tile >> 1)) * 4) * 4);
    }
    // no sync: this warp overwrites only its own Q rows with P later

    float m0r = -1e30f, m1r = -1e30f, l0 = 0.f, l1 = 0.f;
    float oacc[8][4] = {};

    int ntiles = t0 / 64 + 2;
    for (int it = 0; it < ntiles; it++) {
        int s0 = it * 64;
        // K via cp.async
        #pragma unroll
        for (int i = 0; i < 4; i++) {
            int ch = tid + 256 * i;
            int r = ch >> 4, sg = ch & 15;
            cp16(sK + (uint32_t)(r * 68 + sg * 4) * 4,
                 Kp + (size_t)(s0 + r) * DD + sg * 4);
        }
        cp_commit();
        // V transpose staging (overlaps K copy)
        #pragma unroll
        for (int i = 0; i < 4; i++) {
            int idx = tid + 256 * i;
            int s = idx >> 4, d4 = (idx & 15) * 4;
            float4 vv = *(const float4*)(Vp + (size_t)(s0 + s) * DD + d4);
            int swz = (d4 >> 2) & 15;
            int pc = 4 * ((s >> 2) ^ swz) + (s & 3);
            Vtm[(d4 + 0) * 68 + pc] = vv.x;
            Vtm[(d4 + 1) * 68 + pc] = vv.y;
            Vtm[(d4 + 2) * 68 + pc] = vv.z;
            Vtm[(d4 + 3) * 68 + pc] = vv.w;
        }
        cp_wait<0>();
        __syncthreads();

        // S = Q @ K^T
        float sacc[8][4] = {};
        #pragma unroll
        for (int ks = 0; ks < 8; ks++) {
            #pragma unroll
            for (int nj2 = 0; nj2 < 4; nj2++) {
                unsigned r0, r1, r2, r3;
                int row = nj2 * 16 + (tile >> 1) * 8 + rl;
                int seg = 2 * ks + (tile & 1);
                ldsm4(r0, r1, r2, r3, sK + (uint32_t)(row * 68 + seg * 4) * 4);
                unsigned b0[2] = {r0, r1}, b1[2] = {r2, r3};
                mma_tf32(sacc[2 * nj2], qa[ks], b0);
                mma_tf32(sacc[2 * nj2 + 1], qa[ks], b1);
            }
        }

        // causal mask (tiles overlapping/above the diagonal)
        if (s0 >= t0) {
            int off = s0 - t0;
            #pragma unroll
            for (int nj = 0; nj < 8; nj++) {
                int c0 = nj * 8 + 2 * t + off, c1 = c0 + 1;
                int r0 = wr + g, r1 = r0 + 8;
                if (c0 > r0) sacc[nj][0] = -1e30f;
                if (c1 > r0) sacc[nj][1] = -1e30f;
                if (c0 > r1) sacc[nj][2] = -1e30f;
                if (c1 > r1) sacc[nj][3] = -1e30f;
            }
        }

        // online softmax (rows wr+g, wr+8+g)
        float mt0 = -1e30f, mt1 = -1e30f;
        #pragma unroll
        for (int nj = 0; nj < 8; nj++) {
            mt0 = fmaxf(mt0, fmaxf(sacc[nj][0], sacc[nj][1]));
            mt1 = fmaxf(mt1, fmaxf(sacc[nj][2], sacc[nj][3]));
        }
        #pragma unroll
        for (int o = 1; o <= 2; o <<= 1) {
            mt0 = fmaxf(mt0, __shfl_xor_sync(0xffffffffu, mt0, o));
            mt1 = fmaxf(mt1, __shfl_xor_sync(0xffffffffu, mt1, o));
        }
        float mn0 = fmaxf(m0r, mt0), mn1 = fmaxf(m1r, mt1);
        float sc0 = __expf(m0r - mn0), sc1 = __expf(m1r - mn1);
        float sum0 = 0.f, sum1 = 0.f;
        #pragma unroll
        for (int nj = 0; nj < 8; nj++) {
            float p00 = __expf(sacc[nj][0] - mn0);
            float p01 = __expf(sacc[nj][1] - mn0);
            float p10 = __expf(sacc[nj][2] - mn1);
            float p11 = __expf(sacc[nj][3] - mn1);
            sum0 += p00 + p01; sum1 += p10 + p11;
            int c = nj * 8 + 2 * t;
            Ps[(wr + g) * 68 + c]     = f2tff(p00);
            Ps[(wr + g) * 68 + c + 1] = f2tff(p01);
            Ps[(wr + 8 + g) * 68 + c]     = f2tff(p10);
            Ps[(wr + 8 + g) * 68 + c + 1] = f2tff(p11);
        }
        #pragma unroll
        for (int o = 1; o <= 2; o <<= 1) {
            sum0 += __shfl_xor_sync(0xffffffffu, sum0, o);
            sum1 += __shfl_xor_sync(0xffffffffu, sum1, o);
        }
        l0 = l0 * sc0 + sum0;
        l1 = l1 * sc1 + sum1;
        m0r = mn0; m1r = mn1;
        #pragma unroll
        for (int nj = 0; nj < 8; nj++) {
            oacc[nj][0] *= sc0; oacc[nj][1] *= sc0;
            oacc[nj][2] *= sc1; oacc[nj][3] *= sc1;
        }
        __syncwarp();   // P rows are warp-local: STS -> LDSM ordering

        // O += P @ V
        #pragma unroll
        for (int j = 0; j < 8; j++) {
            unsigned pa[4];
            {
                int row = wr + (tile & 1) * 8 + rl;
                int seg = 2 * j + (tile >> 1);
                ldsm4(pa[0], pa[1], pa[2], pa[3],
                      sP + (uint32_t)(row * 68 + seg * 4) * 4);
            }
            #pragma unroll
            for (int nj2 = 0; nj2 < 4; nj2++) {
                unsigned r0, r1, r2, r3;
                int row = nj2 * 16 + (tile >> 1) * 8 + rl;
                int lsg = 2 * j + (tile & 1);
                int psg = lsg ^ ((row >> 2) & 15);
                ldsm4(r0, r1, r2, r3, sV + (uint32_t)(row * 68 + psg * 4) * 4);
                unsigned b0[2] = {r0, r1}, b1[2] = {r2, r3};
                mma_tf32(oacc[2 * nj2], pa, b0);
                mma_tf32(oacc[2 * nj2 + 1], pa, b1);
            }
        }
        __syncthreads();   // Ksm/Vtm consumed before next tile staging
    }

    float inv0 = 1.f / l0, inv1 = 1.f / l1;
    int b = bh >> 4, hh = bh & 15;
    int tr0 = t0 + wr + g, tr1 = tr0 + 8;
    #pragma unroll
    for (int nj = 0; nj < 8; nj++) {
        int c = hh * DD + nj * 8 + 2 * t;
        float2 o0 = {f2tff(oacc[nj][0] * inv0), f2tff(oacc[nj][1] * inv0)};
        float2 o1 = {f2tff(oacc[nj][2] * inv1), f2tff(oacc[nj][3] * inv1)};
        *(float2*)(out + (size_t)(b * TT + tr0) * CC + c) = o0;
        *(float2*)(out + (size_t)(b * TT + tr1) * CC + c) = o1;
    }
}

// ============================================================
// launch
// ============================================================
extern "C" void kernel_launch(void* const* d_in, const int* in_sizes, int n_in,
                              void* d_out, int out_size) {
    const float* x      = (const float*)d_in[0];
    const float* wq     = (const float*)d_in[1];
    const float* wk     = (const float*)d_in[2];
    const float* wv     = (const float*)d_in[3];
    const float* w_proj = (const float*)d_in[4];
    const float* b_proj = (const float*)d_in[5];
    const float* w1     = (const float*)d_in[6];
    const float* b1     = (const float*)d_in[7];
    const float* w2     = (const float*)d_in[8];
    const float* b2     = (const float*)d_in[9];
    const float* g1     = (const float*)d_in[10];
    const float* be1    = (const float*)d_in[11];
    const float* g2     = (const float*)d_in[12];
    const float* be2    = (const float*)d_in[13];
    float* out = (float*)d_out;

    float *h1, *q, *k, *v, *attn, *x1, *h2, *ff1;
    float *rwq, *rwk, *rwv, *rwp, *rw1, *rw2;
    cudaGetSymbolAddress((void**)&h1, g_h1);
    cudaGetSymbolAddress((void**)&q, g_q);
    cudaGetSymbolAddress((void**)&k, g_k);
    cudaGetSymbolAddress((void**)&v, g_v);
    cudaGetSymbolAddress((void**)&attn, g_attn);
    cudaGetSymbolAddress((void**)&x1, g_x1);
    cudaGetSymbolAddress((void**)&h2, g_h2);
    cudaGetSymbolAddress((void**)&ff1, g_ff1);
    cudaGetSymbolAddress((void**)&rwq, g_rwq);
    cudaGetSymbolAddress((void**)&rwk, g_rwk);
    cudaGetSymbolAddress((void**)&rwv, g_rwv);
    cudaGetSymbolAddress((void**)&rwp, g_rwp);
    cudaGetSymbolAddress((void**)&rw1, g_rw1);
    cudaGetSymbolAddress((void**)&rw2, g_rw2);

    cudaFuncSetAttribute(gemm_mma<false, false>, cudaFuncAttributeMaxDynamicSharedMemorySize, G_SMEM);
    cudaFuncSetAttribute(gemm_mma<true, true>,   cudaFuncAttributeMaxDynamicSharedMemorySize, G_SMEM);
    cudaFuncSetAttribute(qkv_mma, cudaFuncAttributeMaxDynamicSharedMemorySize, Q_SMEM);
    cudaFuncSetAttribute(attn_mma, cudaFuncAttributeMaxDynamicSharedMemorySize, ATT_SMEM);

    // 0. weight pre-round (RNA tf32)
    round_w<<<512, 256>>>(wq, rwq, HH * CC * DD);
    round_w<<<512, 256>>>(wk, rwk, HH * CC * DD);
    round_w<<<512, 256>>>(wv, rwv, HH * CC * DD);
    round_w<<<512, 256>>>(w_proj, rwp, CC * CC);
    round_w<<<1024, 256>>>(w1, rw1, CC * FFDIM);
    round_w<<<1024, 256>>>(w2, rw2, FFDIM * CC);
    // 1. LN1 (rounded out)
    ln_kernel<<<MTOT, 256>>>(x, g1, be1, h1);
    // 2. QKV (rounded out)
    qkv_mma<<<dim3(MTOT / 128, 3 * HH), 128, Q_SMEM>>>(h1, rwq, rwk, rwv, q, k, v);
    // 3. attention (rounded out)
    attn_mma<<<dim3(TT / 128, BBATCH * HH), 256, ATT_SMEM>>>(q, k, v, attn);
    // 4. proj + bias + residual -> x1
    gemm_mma<false, false><<<dim3(CC / 128, MTOT / 128), 256, G_SMEM>>>(attn, rwp, b_proj, x, x1,
                                                                        MTOT, CC, CC);
    // 5. LN2 (rounded out)
    ln_kernel<<<MTOT, 256>>>(x1, g2, be2, h2);
    // 6. FF1 + bias + relu (rounded out)
    gemm_mma<true, true><<<dim3(FFDIM / 128, MTOT / 128), 256, G_SMEM>>>(h2, rw1, b1, nullptr, ff1,
                                                                         MTOT, FFDIM, CC);
    // 7. FF2 + bias + residual -> out
    gemm_mma<false, false><<<dim3(CC / 128, MTOT / 128), 256, G_SMEM>>>(ff1, rw2, b2, x1, out,
                                                                        MTOT, CC, FFDIM);
}

// round 6
// speedup vs baseline: 1.1787x; 1.1787x over previous
#include <cuda_runtime.h>
#include <math.h>
#include <stdint.h>

#define TT 2048
#define CC 1024
#define HH 16
#define DD 64
#define BBATCH 2
#define MTOT (BBATCH * TT)   // 4096
#define FFDIM (4 * CC)       // 4096

// -------- scratch (alloc-free) --------
__device__ float g_h1[MTOT * CC];
__device__ float g_q[MTOT * CC];     // (b,h,t,d)
__device__ float g_k[MTOT * CC];
__device__ float g_v[MTOT * CC];
__device__ float g_attn[MTOT * CC];
__device__ float g_x1[MTOT * CC];
__device__ float g_h2[MTOT * CC];
__device__ float g_ff1[MTOT * FFDIM];

// -------- helpers --------
__device__ __forceinline__ unsigned f2tf(float f) {
    unsigned u;
    asm("cvt.rna.tf32.f32 %0, %1;" : "=r"(u) : "f"(f));
    return u;
}
__device__ __forceinline__ void mma_tf32(float* c, const unsigned* a, const unsigned* b) {
    asm volatile(
        "mma.sync.aligned.m16n8k8.row.col.f32.tf32.tf32.f32 "
        "{%0,%1,%2,%3}, {%4,%5,%6,%7}, {%8,%9}, {%0,%1,%2,%3};"
        : "+f"(c[0]), "+f"(c[1]), "+f"(c[2]), "+f"(c[3])
        : "r"(a[0]), "r"(a[1]), "r"(a[2]), "r"(a[3]), "r"(b[0]), "r"(b[1]));
}
__device__ __forceinline__ void cp16(uint32_t s, const void* g) {
    asm volatile("cp.async.ca.shared.global [%0], [%1], 16;" :: "r"(s), "l"(g));
}
__device__ __forceinline__ void cp_commit() { asm volatile("cp.async.commit_group;"); }
template <int N>
__device__ __forceinline__ void cp_wait() { asm volatile("cp.async.wait_group %0;" :: "n"(N)); }
__device__ __forceinline__ void ldsm4(unsigned& r0, unsigned& r1, unsigned& r2, unsigned& r3,
                                      uint32_t a) {
    asm volatile("ldmatrix.sync.aligned.m8n8.x4.shared.b16 {%0,%1,%2,%3}, [%4];"
                 : "=r"(r0), "=r"(r1), "=r"(r2), "=r"(r3) : "r"(a));
}

// ============================================================
// LayerNorm: one block (256 thr) per row of 1024
// ============================================================
__global__ void ln_kernel(const float* __restrict__ x, const float* __restrict__ g,
                          const float* __restrict__ b, float* __restrict__ out) {
    __shared__ float red[8];
    __shared__ float s_mu, s_rstd;
    int row = blockIdx.x;
    int tid = threadIdx.x;
    const float* xr = x + (size_t)row * CC;

    float v0 = xr[tid], v1 = xr[tid + 256], v2 = xr[tid + 512], v3 = xr[tid + 768];
    float s = v0 + v1 + v2 + v3;
    #pragma unroll
    for (int o = 16; o > 0; o >>= 1) s += __shfl_xor_sync(0xffffffffu, s, o);
    if ((tid & 31) == 0) red[tid >> 5] = s;
    __syncthreads();
    if (tid == 0) {
        float t = 0.f;
        #pragma unroll
        for (int i = 0; i < 8; i++) t += red[i];
        s_mu = t * (1.0f / CC);
    }
    __syncthreads();
    float mu = s_mu;
    float d0 = v0 - mu, d1 = v1 - mu, d2 = v2 - mu, d3 = v3 - mu;
    float s2 = d0 * d0 + d1 * d1 + d2 * d2 + d3 * d3;
    #pragma unroll
    for (int o = 16; o > 0; o >>= 1) s2 += __shfl_xor_sync(0xffffffffu, s2, o);
    __syncthreads();
    if ((tid & 31) == 0) red[tid >> 5] = s2;
    __syncthreads();
    if (tid == 0) {
        float t = 0.f;
        #pragma unroll
        for (int i = 0; i < 8; i++) t += red[i];
        s_rstd = rsqrtf(t * (1.0f / CC) + 1e-5f);
    }
    __syncthreads();
    float rstd = s_rstd;
    float* orow = out + (size_t)row * CC;
    orow[tid]       = d0 * rstd * g[tid]       + b[tid];
    orow[tid + 256] = d1 * rstd * g[tid + 256] + b[tid + 256];
    orow[tid + 512] = d2 * rstd * g[tid + 512] + b[tid + 512];
    orow[tid + 768] = d3 * rstd * g[tid + 768] + b[tid + 768];
}

// ============================================================
// tf32 GEMM, cp.async 2-stage, ldmatrix A-frags (round-4 form).
// BM=128, BN=128, BK=32, 256 thr = 8 warps (2x4), warp tile 64x32.
// ============================================================
#define G_ASTG (128 * 36)
#define G_BSTG (32 * 136)
#define G_SMEM ((2 * (G_ASTG + G_BSTG)) * 4)

template <bool RELU>
__global__ __launch_bounds__(256) void gemm_mma(
    const float* __restrict__ A, const float* __restrict__ Bm,
    const float* __restrict__ bias, const float* __restrict__ res,
    float* __restrict__ C, int M, int N, int K) {
    extern __shared__ float smx[];
    float* Bsm = smx + 2 * G_ASTG;
    uint32_t sA = (uint32_t)__cvta_generic_to_shared(smx);
    uint32_t sB = (uint32_t)__cvta_generic_to_shared(Bsm);

    int tid = threadIdx.x;
    int warp = tid >> 5, lane = tid & 31;
    int g = lane >> 2, t = lane & 3;
    int tile = lane >> 3, rl = lane & 7;
    int wm = (warp >> 2) * 64, wn = (warp & 3) * 32;
    int m0 = blockIdx.y * 128, n0 = blockIdx.x * 128;

    float acc[4][4][4] = {};
    int a_rbase = wm + (tile & 1) * 8 + rl;
    int a_sbase = (tile >> 1);

    auto pre = [&](int st, int k0) {
        #pragma unroll
        for (int i = 0; i < 4; i++) {
            int ch = tid + 256 * i;
            int r = ch >> 3, sg = ch & 7;
            cp16(sA + (uint32_t)(st * G_ASTG + r * 36 + sg * 4) * 4,
                 A + (size_t)(m0 + r) * K + k0 + sg * 4);
        }
        #pragma unroll
        for (int i = 0; i < 4; i++) {
            int ch = tid + 256 * i;
            int r = ch >> 5, c = (ch & 31) * 4;
            cp16(sB + (uint32_t)(st * G_BSTG + r * 136 + c) * 4,
                 Bm + (size_t)(k0 + r) * N + n0 + c);
        }
        cp_commit();
    };

    pre(0, 0);
    int nk = K >> 5;
    for (int kk = 0; kk < nk; kk++) {
        int st = kk & 1;
        if (kk + 1 < nk) { pre(st ^ 1, (kk + 1) << 5); cp_wait<1>(); }
        else cp_wait<0>();
        __syncthreads();

        const float* bsp = Bsm + st * G_BSTG;
        uint32_t sAs = sA + (uint32_t)(st * G_ASTG) * 4;
        #pragma unroll
        for (int ks = 0; ks < 4; ks++) {
            unsigned af[4][4];
            #pragma unroll
            for (int mi = 0; mi < 4; mi++) {
                ldsm4(af[mi][0], af[mi][1], af[mi][2], af[mi][3],
                      sAs + (uint32_t)((a_rbase + mi * 16) * 36 + (2 * ks + a_sbase) * 4) * 4);
            }
            #pragma unroll
            for (int nj = 0; nj < 4; nj++) {
                unsigned bf[2];
                bf[0] = __float_as_uint(bsp[(ks * 8 + t) * 136 + wn + nj * 8 + g]);
                bf[1] = __float_as_uint(bsp[(ks * 8 + t + 4) * 136 + wn + nj * 8 + g]);
                #pragma unroll
                for (int mi = 0; mi < 4; mi++) mma_tf32(acc[mi][nj], af[mi], bf);
            }
        }
        __syncthreads();
    }

    #pragma unroll
    for (int mi = 0; mi < 4; mi++) {
        #pragma unroll
        for (int nj = 0; nj < 4; nj++) {
            int c = n0 + wn + nj * 8 + 2 * t;
            int r0 = m0 + wm + mi * 16 + g;
            int r1 = r0 + 8;
            float2 o0 = {acc[mi][nj][0], acc[mi][nj][1]};
            float2 o1 = {acc[mi][nj][2], acc[mi][nj][3]};
            if (bias) {
                float2 bv = *(const float2*)(bias + c);
                o0.x += bv.x; o0.y += bv.y; o1.x += bv.x; o1.y += bv.y;
            }
            if (res) {
                float2 ra = *(const float2*)(res + (size_t)r0 * N + c);
                float2 rb = *(const float2*)(res + (size_t)r1 * N + c);
                o0.x += ra.x; o0.y += ra.y; o1.x += rb.x; o1.y += rb.y;
            }
            if (RELU) {
                o0.x = fmaxf(o0.x, 0.f); o0.y = fmaxf(o0.y, 0.f);
                o1.x = fmaxf(o1.x, 0.f); o1.y = fmaxf(o1.y, 0.f);
            }
            *(float2*)(C + (size_t)r0 * N + c) = o0;
            *(float2*)(C + (size_t)r1 * N + c) = o1;
        }
    }
}

// ============================================================
// Merged QKV GEMM: 2 heads per CTA, BN=128, 256 thr (gemm shape).
// grid = (MTOT/128, 3 * HH/2). B tile gathered from 2 per-head
// 64-wide weight blocks; epilogue scatters per 64-col group.
// Same k-loop/mma order as round-4 qkv -> bitwise-identical results.
// ============================================================
__global__ __launch_bounds__(256) void qkv_mma2(
    const float* __restrict__ h, const float* __restrict__ wq,
    const float* __restrict__ wk, const float* __restrict__ wv,
    float* __restrict__ q, float* __restrict__ k, float* __restrict__ v) {
    extern __shared__ float smx[];
    float* Bsm = smx + 2 * G_ASTG;
    uint32_t sA = (uint32_t)__cvta_generic_to_shared(smx);
    uint32_t sB = (uint32_t)__cvta_generic_to_shared(Bsm);

    int which = blockIdx.y >> 3;          // 0,1,2
    int hp = blockIdx.y & 7;              // head pair: heads 2hp, 2hp+1
    const float* Wb = (which == 0 ? wq : (which == 1 ? wk : wv));
    float* O = (which == 0 ? q : (which == 1 ? k : v));

    int tid = threadIdx.x;
    int warp = tid >> 5, lane = tid & 31;
    int g = lane >> 2, t = lane & 3;
    int tile = lane >> 3, rl = lane & 7;
    int wm = (warp >> 2) * 64, wn = (warp & 3) * 32;
    int m0 = blockIdx.x * 128;

    float acc[4][4][4] = {};
    int a_rbase = wm + (tile & 1) * 8 + rl;
    int a_sbase = (tile >> 1);

    auto pre = [&](int st, int k0) {
        #pragma unroll
        for (int i = 0; i < 4; i++) {
            int ch = tid + 256 * i;
            int r = ch >> 3, sg = ch & 7;
            cp16(sA + (uint32_t)(st * G_ASTG + r * 36 + sg * 4) * 4,
                 h + (size_t)(m0 + r) * CC + k0 + sg * 4);
        }
        #pragma unroll
        for (int i = 0; i < 4; i++) {
            int ch = tid + 256 * i;
            int r = ch >> 5, c = (ch & 31) * 4;     // c in [0,128), 4-aligned
            int head = 2 * hp + (c >> 6);
            cp16(sB + (uint32_t)(st * G_BSTG + r * 136 + c) * 4,
                 Wb + (size_t)head * CC * DD + (size_t)(k0 + r) * DD + (c & 63));
        }
        cp_commit();
    };

    pre(0, 0);
    int nk = CC >> 5;
    for (int kk = 0; kk < nk; kk++) {
        int st = kk & 1;
        if (kk + 1 < nk) { pre(st ^ 1, (kk + 1) << 5); cp_wait<1>(); }
        else cp_wait<0>();
        __syncthreads();

        const float* bsp = Bsm + st * G_BSTG;
        uint32_t sAs = sA + (uint32_t)(st * G_ASTG) * 4;
        #pragma unroll
        for (int ks = 0; ks < 4; ks++) {
            unsigned af[4][4];
            #pragma unroll
            for (int mi = 0; mi < 4; mi++) {
                ldsm4(af[mi][0], af[mi][1], af[mi][2], af[mi][3],
                      sAs + (uint32_t)((a_rbase + mi * 16) * 36 + (2 * ks + a_sbase) * 4) * 4);
            }
            #pragma unroll
            for (int nj = 0; nj < 4; nj++) {
                unsigned bf[2];
                bf[0] = __float_as_uint(bsp[(ks * 8 + t) * 136 + wn + nj * 8 + g]);
                bf[1] = __float_as_uint(bsp[(ks * 8 + t + 4) * 136 + wn + nj * 8 + g]);
                #pragma unroll
                for (int mi = 0; mi < 4; mi++) mma_tf32(acc[mi][nj], af[mi], bf);
            }
        }
        __syncthreads();
    }

    #pragma unroll
    for (int mi = 0; mi < 4; mi++) {
        #pragma unroll
        for (int nj = 0; nj < 4; nj++) {
            int c = wn + nj * 8 + 2 * t;          // [0,128), even
            int head = 2 * hp + (c >> 6);
            int d = c & 63;
            int m0r = m0 + wm + mi * 16 + g;
            int m1r = m0r + 8;
            int b0 = m0r >> 11, t0i = m0r & (TT - 1);
            int b1 = m1r >> 11, t1i = m1r & (TT - 1);
            float2 o0 = {acc[mi][nj][0], acc[mi][nj][1]};
            float2 o1 = {acc[mi][nj][2], acc[mi][nj][3]};
            *(float2*)(O + (((size_t)(b0 * HH + head) * TT + t0i) << 6) + d) = o0;
            *(float2*)(O + (((size_t)(b1 * HH + head) * TT + t1i) << 6) + d) = o1;
        }
    }
}

// ============================================================
// Flash attention (round-4 form). Br=64, Bc=64, 128 thr (4 warps).
// K via cp.async (key-major), V transposed+swizzled, P aliases Ks.
// All fragments via ldmatrix. Scale 1/8 folded into Q (RNA cvt).
// ============================================================
__global__ __launch_bounds__(128) void attn_mma(
    const float* __restrict__ Q, const float* __restrict__ K,
    const float* __restrict__ V, float* __restrict__ out) {
    __shared__ float Ks[64 * 68];   // K tile (key-major) / aliased P tile (row-major)
    __shared__ float Vt[64 * 68];   // V transposed [d][key], seg-swizzled

    int bh = blockIdx.y;
    int t0 = blockIdx.x * 64;
    const float* Qp = Q + (size_t)bh * TT * DD;
    const float* Kp = K + (size_t)bh * TT * DD;
    const float* Vp = V + (size_t)bh * TT * DD;
    uint32_t sK = (uint32_t)__cvta_generic_to_shared(Ks);
    uint32_t sV = (uint32_t)__cvta_generic_to_shared(Vt);

    int tid = threadIdx.x;
    int warp = tid >> 5, lane = tid & 31;
    int g = lane >> 2, t = lane & 3;
    int tile = lane >> 3, rl = lane & 7;
    int wr = warp * 16;

    // stage Q (scaled, RNA tf32) into Ks, pull A-frags via ldmatrix
    #pragma unroll
    for (int i = 0; i < 8; i++) {
        int idx = tid + 128 * i;
        int r = idx >> 4, c4 = (idx & 15) * 4;
        float4 qv = *(const float4*)(Qp + (size_t)(t0 + r) * DD + c4);
        uint4 u = {f2tf(qv.x * 0.125f), f2tf(qv.y * 0.125f),
                   f2tf(qv.z * 0.125f), f2tf(qv.w * 0.125f)};
        *(uint4*)&Ks[r * 68 + c4] = u;
    }
    __syncthreads();
    unsigned qa[8][4];
    {
        int row = wr + (tile & 1) * 8 + rl;
        #pragma unroll
        for (int ks = 0; ks < 8; ks++)
            ldsm4(qa[ks][0], qa[ks][1], qa[ks][2], qa[ks][3],
                  sK + (uint32_t)(row * 68 + (2 * ks + (tile >> 1)) * 4) * 4);
    }
    __syncthreads();

    float m0r = -1e30f, m1r = -1e30f, l0 = 0.f, l1 = 0.f;
    float oacc[8][4] = {};

    int ntiles = t0 / 64 + 1;
    for (int it = 0; it < ntiles; it++) {
        int s0 = it * 64;
        // K via cp.async (raw fp32 -> tf32 truncation)
        #pragma unroll
        for (int i = 0; i < 8; i++) {
            int ch = tid + 128 * i;
            int r = ch >> 4, sg = ch & 15;
            cp16(sK + (uint32_t)(r * 68 + sg * 4) * 4,
                 Kp + (size_t)(s0 + r) * DD + sg * 4);
        }
        cp_commit();
        // V transpose staging (overlaps K copy)
        #pragma unroll
        for (int i = 0; i < 8; i++) {
            int idx = tid + 128 * i;
            int s = idx >> 4, d4 = (idx & 15) * 4;
            float4 vv = *(const float4*)(Vp + (size_t)(s0 + s) * DD + d4);
            int swz = (d4 >> 2) & 15;
            int pc = 4 * ((s >> 2) ^ swz) + (s & 3);
            Vt[(d4 + 0) * 68 + pc] = vv.x;
            Vt[(d4 + 1) * 68 + pc] = vv.y;
            Vt[(d4 + 2) * 68 + pc] = vv.z;
            Vt[(d4 + 3) * 68 + pc] = vv.w;
        }
        cp_wait<0>();
        __syncthreads();

        // S = Q @ K^T
        float sacc[8][4] = {};
        #pragma unroll
        for (int ks = 0; ks < 8; ks++) {
            #pragma unroll
            for (int nj2 = 0; nj2 < 4; nj2++) {
                unsigned r0, r1, r2, r3;
                int row = nj2 * 16 + (tile >> 1) * 8 + rl;
                int seg = 2 * ks + (tile & 1);
                ldsm4(r0, r1, r2, r3, sK + (uint32_t)(row * 68 + seg * 4) * 4);
                unsigned b0[2] = {r0, r1}, b1[2] = {r2, r3};
                mma_tf32(sacc[2 * nj2], qa[ks], b0);
                mma_tf32(sacc[2 * nj2 + 1], qa[ks], b1);
            }
        }
        __syncthreads();   // Ks reads done before P overwrite

        // causal mask (diagonal tile only)
        if (s0 == t0) {
            #pragma unroll
            for (int nj = 0; nj < 8; nj++) {
                int c0 = nj * 8 + 2 * t, c1 = c0 + 1;
                int r0 = wr + g, r1 = r0 + 8;
                if (c0 > r0) sacc[nj][0] = -1e30f;
                if (c1 > r0) sacc[nj][1] = -1e30f;
                if (c0 > r1) sacc[nj][2] = -1e30f;
                if (c1 > r1) sacc[nj][3] = -1e30f;
            }
        }

        // online softmax
        float mt0 = -1e30f, mt1 = -1e30f;
        #pragma unroll
        for (int nj = 0; nj < 8; nj++) {
            mt0 = fmaxf(mt0, fmaxf(sacc[nj][0], sacc[nj][1]));
            mt1 = fmaxf(mt1, fmaxf(sacc[nj][2], sacc[nj][3]));
        }
        #pragma unroll
        for (int o = 1; o <= 2; o <<= 1) {
            mt0 = fmaxf(mt0, __shfl_xor_sync(0xffffffffu, mt0, o));
            mt1 = fmaxf(mt1, __shfl_xor_sync(0xffffffffu, mt1, o));
        }
        float mn0 = fmaxf(m0r, mt0), mn1 = fmaxf(m1r, mt1);
        float sc0 = __expf(m0r - mn0), sc1 = __expf(m1r - mn1);
        float sum0 = 0.f, sum1 = 0.f;
        #pragma unroll
        for (int nj = 0; nj < 8; nj++) {
            float p00 = __expf(sacc[nj][0] - mn0);
            float p01 = __expf(sacc[nj][1] - mn0);
            float p10 = __expf(sacc[nj][2] - mn1);
            float p11 = __expf(sacc[nj][3] - mn1);
            sum0 += p00 + p01; sum1 += p10 + p11;
            int c = nj * 8 + 2 * t;
            Ks[(wr + g) * 68 + c] = p00;     Ks[(wr + g) * 68 + c + 1] = p01;
            Ks[(wr + 8 + g) * 68 + c] = p10; Ks[(wr + 8 + g) * 68 + c + 1] = p11;
        }
        #pragma unroll
        for (int o = 1; o <= 2; o <<= 1) {
            sum0 += __shfl_xor_sync(0xffffffffu, sum0, o);
            sum1 += __shfl_xor_sync(0xffffffffu, sum1, o);
        }
        l0 = l0 * sc0 + sum0;
        l1 = l1 * sc1 + sum1;
        m0r = mn0; m1r = mn1;
        #pragma unroll
        for (int nj = 0; nj < 8; nj++) {
            oacc[nj][0] *= sc0; oacc[nj][1] *= sc0;
            oacc[nj][2] *= sc1; oacc[nj][3] *= sc1;
        }
        __syncthreads();   // P visible to all warps

        // O += P @ V
        #pragma unroll
        for (int j = 0; j < 8; j++) {
            unsigned pa[4];
            {
                int row = wr + (tile & 1) * 8 + rl;
                int seg = 2 * j + (tile >> 1);
                ldsm4(pa[0], pa[1], pa[2], pa[3],
                      sK + (uint32_t)(row * 68 + seg * 4) * 4);
            }
            #pragma unroll
            for (int nj2 = 0; nj2 < 4; nj2++) {
                unsigned r0, r1, r2, r3;
                int row = nj2 * 16 + (tile >> 1) * 8 + rl;
                int lsg = 2 * j + (tile & 1);
                int psg = lsg ^ ((row >> 2) & 15);
                ldsm4(r0, r1, r2, r3, sV + (uint32_t)(row * 68 + psg * 4) * 4);
                unsigned b0[2] = {r0, r1}, b1[2] = {r2, r3};
                mma_tf32(oacc[2 * nj2], pa, b0);
                mma_tf32(oacc[2 * nj2 + 1], pa, b1);
            }
        }
        __syncthreads();
    }

    float inv0 = 1.f / l0, inv1 = 1.f / l1;
    int b = bh >> 4, hh = bh & 15;
    int tr0 = t0 + wr + g, tr1 = tr0 + 8;
    #pragma unroll
    for (int nj = 0; nj < 8; nj++) {
        int c = hh * DD + nj * 8 + 2 * t;
        float2 o0 = {oacc[nj][0] * inv0, oacc[nj][1] * inv0};
        float2 o1 = {oacc[nj][2] * inv1, oacc[nj][3] * inv1};
        *(float2*)(out + (size_t)(b * TT + tr0) * CC + c) = o0;
        *(float2*)(out + (size_t)(b * TT + tr1) * CC + c) = o1;
    }
}

// ============================================================
// launch
// ============================================================
extern "C" void kernel_launch(void* const* d_in, const int* in_sizes, int n_in,
                              void* d_out, int out_size) {
    const float* x      = (const float*)d_in[0];
    const float* wq     = (const float*)d_in[1];
    const float* wk     = (const float*)d_in[2];
    const float* wv     = (const float*)d_in[3];
    const float* w_proj = (const float*)d_in[4];
    const float* b_proj = (const float*)d_in[5];
    const float* w1     = (const float*)d_in[6];
    const float* b1     = (const float*)d_in[7];
    const float* w2     = (const float*)d_in[8];
    const float* b2     = (const float*)d_in[9];
    const float* g1     = (const float*)d_in[10];
    const float* be1    = (const float*)d_in[11];
    const float* g2     = (const float*)d_in[12];
    const float* be2    = (const float*)d_in[13];
    float* out = (float*)d_out;

    float *h1, *q, *k, *v, *attn, *x1, *h2, *ff1;
    cudaGetSymbolAddress((void**)&h1, g_h1);
    cudaGetSymbolAddress((void**)&q, g_q);
    cudaGetSymbolAddress((void**)&k, g_k);
    cudaGetSymbolAddress((void**)&v, g_v);
    cudaGetSymbolAddress((void**)&attn, g_attn);
    cudaGetSymbolAddress((void**)&x1, g_x1);
    cudaGetSymbolAddress((void**)&h2, g_h2);
    cudaGetSymbolAddress((void**)&ff1, g_ff1);

    cudaFuncSetAttribute(gemm_mma<false>, cudaFuncAttributeMaxDynamicSharedMemorySize, G_SMEM);
    cudaFuncSetAttribute(gemm_mma<true>,  cudaFuncAttributeMaxDynamicSharedMemorySize, G_SMEM);
    cudaFuncSetAttribute(qkv_mma2, cudaFuncAttributeMaxDynamicSharedMemorySize, G_SMEM);

    // 1. LN1
    ln_kernel<<<MTOT, 256>>>(x, g1, be1, h1);
    // 2. QKV (merged: 2 heads per CTA)
    qkv_mma2<<<dim3(MTOT / 128, 3 * (HH / 2)), 256, G_SMEM>>>(h1, wq, wk, wv, q, k, v);
    // 3. attention
    attn_mma<<<dim3(TT / 64, BBATCH * HH), 128>>>(q, k, v, attn);
    // 4. proj + bias + residual -> x1
    gemm_mma<false><<<dim3(CC / 128, MTOT / 128), 256, G_SMEM>>>(attn, w_proj, b_proj, x, x1,
                                                                 MTOT, CC, CC);
    // 5. LN2
    ln_kernel<<<MTOT, 256>>>(x1, g2, be2, h2);
    // 6. FF1 + bias + relu
    gemm_mma<true><<<dim3(FFDIM / 128, MTOT / 128), 256, G_SMEM>>>(h2, w1, b1, nullptr, ff1,
                                                                   MTOT, FFDIM, CC);
    // 7. FF2 + bias + residual -> out
    gemm_mma<false><<<dim3(CC / 128, MTOT / 128), 256, G_SMEM>>>(ff1, w2, b2, x1, out,
                                                                 MTOT, CC, FFDIM);
}

// round 8
// speedup vs baseline: 1.1991x; 1.0173x over previous
#include <cuda_runtime.h>
#include <math.h>
#include <stdint.h>

#define TT 2048
#define CC 1024
#define HH 16
#define DD 64
#define BBATCH 2
#define MTOT (BBATCH * TT)   // 4096
#define FFDIM (4 * CC)       // 4096

// -------- scratch (alloc-free) --------
__device__ float g_h1[MTOT * CC];
__device__ float g_q[MTOT * CC];     // (b,h,t,d)
__device__ float g_k[MTOT * CC];     // (b,h,t,d)
__device__ float g_v[MTOT * CC];     // (b,h,d,t)  <-- transposed
__device__ float g_attn[MTOT * CC];
__device__ float g_x1[MTOT * CC];
__device__ float g_h2[MTOT * CC];
__device__ float g_ff1[MTOT * FFDIM];

// -------- helpers --------
__device__ __forceinline__ unsigned f2tf(float f) {
    unsigned u;
    asm("cvt.rna.tf32.f32 %0, %1;" : "=r"(u) : "f"(f));
    return u;
}
__device__ __forceinline__ void mma_tf32(float* c, const unsigned* a, const unsigned* b) {
    asm volatile(
        "mma.sync.aligned.m16n8k8.row.col.f32.tf32.tf32.f32 "
        "{%0,%1,%2,%3}, {%4,%5,%6,%7}, {%8,%9}, {%0,%1,%2,%3};"
        : "+f"(c[0]), "+f"(c[1]), "+f"(c[2]), "+f"(c[3])
        : "r"(a[0]), "r"(a[1]), "r"(a[2]), "r"(a[3]), "r"(b[0]), "r"(b[1]));
}
__device__ __forceinline__ void cp16(uint32_t s, const void* g) {
    asm volatile("cp.async.ca.shared.global [%0], [%1], 16;" :: "r"(s), "l"(g));
}
__device__ __forceinline__ void cp_commit() { asm volatile("cp.async.commit_group;"); }
template <int N>
__device__ __forceinline__ void cp_wait() { asm volatile("cp.async.wait_group %0;" :: "n"(N)); }
__device__ __forceinline__ void ldsm4(unsigned& r0, unsigned& r1, unsigned& r2, unsigned& r3,
                                      uint32_t a) {
    asm volatile("ldmatrix.sync.aligned.m8n8.x4.shared.b16 {%0,%1,%2,%3}, [%4];"
                 : "=r"(r0), "=r"(r1), "=r"(r2), "=r"(r3) : "r"(a));
}

// ============================================================
// LayerNorm: one block (256 thr) per row of 1024
// ============================================================
__global__ void ln_kernel(const float* __restrict__ x, const float* __restrict__ g,
                          const float* __restrict__ b, float* __restrict__ out) {
    __shared__ float red[8];
    __shared__ float s_mu, s_rstd;
    int row = blockIdx.x;
    int tid = threadIdx.x;
    const float* xr = x + (size_t)row * CC;

    float v0 = xr[tid], v1 = xr[tid + 256], v2 = xr[tid + 512], v3 = xr[tid + 768];
    float s = v0 + v1 + v2 + v3;
    #pragma unroll
    for (int o = 16; o > 0; o >>= 1) s += __shfl_xor_sync(0xffffffffu, s, o);
    if ((tid & 31) == 0) red[tid >> 5] = s;
    __syncthreads();
    if (tid == 0) {
        float t = 0.f;
        #pragma unroll
        for (int i = 0; i < 8; i++) t += red[i];
        s_mu = t * (1.0f / CC);
    }
    __syncthreads();
    float mu = s_mu;
    float d0 = v0 - mu, d1 = v1 - mu, d2 = v2 - mu, d3 = v3 - mu;
    float s2 = d0 * d0 + d1 * d1 + d2 * d2 + d3 * d3;
    #pragma unroll
    for (int o = 16; o > 0; o >>= 1) s2 += __shfl_xor_sync(0xffffffffu, s2, o);
    __syncthreads();
    if ((tid & 31) == 0) red[tid >> 5] = s2;
    __syncthreads();
    if (tid == 0) {
        float t = 0.f;
        #pragma unroll
        for (int i = 0; i < 8; i++) t += red[i];
        s_rstd = rsqrtf(t * (1.0f / CC) + 1e-5f);
    }
    __syncthreads();
    float rstd = s_rstd;
    float* orow = out + (size_t)row * CC;
    orow[tid]       = d0 * rstd * g[tid]       + b[tid];
    orow[tid + 256] = d1 * rstd * g[tid + 256] + b[tid + 256];
    orow[tid + 512] = d2 * rstd * g[tid + 512] + b[tid + 512];
    orow[tid + 768] = d3 * rstd * g[tid + 768] + b[tid + 768];
}

// ============================================================
// tf32 GEMM, cp.async 2-stage, ldmatrix A-frags (round-4 form).
// BM=128, BN=128, BK=32, 256 thr = 8 warps (2x4), warp tile 64x32.
// ============================================================
#define G_ASTG (128 * 36)
#define G_BSTG (32 * 136)
#define G_SMEM ((2 * (G_ASTG + G_BSTG)) * 4)

template <bool RELU>
__global__ __launch_bounds__(256) void gemm_mma(
    const float* __restrict__ A, const float* __restrict__ Bm,
    const float* __restrict__ bias, const float* __restrict__ res,
    float* __restrict__ C, int M, int N, int K) {
    extern __shared__ float smx[];
    float* Bsm = smx + 2 * G_ASTG;
    uint32_t sA = (uint32_t)__cvta_generic_to_shared(smx);
    uint32_t sB = (uint32_t)__cvta_generic_to_shared(Bsm);

    int tid = threadIdx.x;
    int warp = tid >> 5, lane = tid & 31;
    int g = lane >> 2, t = lane & 3;
    int tile = lane >> 3, rl = lane & 7;
    int wm = (warp >> 2) * 64, wn = (warp & 3) * 32;
    int m0 = blockIdx.y * 128, n0 = blockIdx.x * 128;

    float acc[4][4][4] = {};
    int a_rbase = wm + (tile & 1) * 8 + rl;
    int a_sbase = (tile >> 1);

    auto pre = [&](int st, int k0) {
        #pragma unroll
        for (int i = 0; i < 4; i++) {
            int ch = tid + 256 * i;
            int r = ch >> 3, sg = ch & 7;
            cp16(sA + (uint32_t)(st * G_ASTG + r * 36 + sg * 4) * 4,
                 A + (size_t)(m0 + r) * K + k0 + sg * 4);
        }
        #pragma unroll
        for (int i = 0; i < 4; i++) {
            int ch = tid + 256 * i;
            int r = ch >> 5, c = (ch & 31) * 4;
            cp16(sB + (uint32_t)(st * G_BSTG + r * 136 + c) * 4,
                 Bm + (size_t)(k0 + r) * N + n0 + c);
        }
        cp_commit();
    };

    pre(0, 0);
    int nk = K >> 5;
    for (int kk = 0; kk < nk; kk++) {
        int st = kk & 1;
        if (kk + 1 < nk) { pre(st ^ 1, (kk + 1) << 5); cp_wait<1>(); }
        else cp_wait<0>();
        __syncthreads();

        const float* bsp = Bsm + st * G_BSTG;
        uint32_t sAs = sA + (uint32_t)(st * G_ASTG) * 4;
        #pragma unroll
        for (int ks = 0; ks < 4; ks++) {
            unsigned af[4][4];
            #pragma unroll
            for (int mi = 0; mi < 4; mi++) {
                ldsm4(af[mi][0], af[mi][1], af[mi][2], af[mi][3],
                      sAs + (uint32_t)((a_rbase + mi * 16) * 36 + (2 * ks + a_sbase) * 4) * 4);
            }
            #pragma unroll
            for (int nj = 0; nj < 4; nj++) {
                unsigned bf[2];
                bf[0] = __float_as_uint(bsp[(ks * 8 + t) * 136 + wn + nj * 8 + g]);
                bf[1] = __float_as_uint(bsp[(ks * 8 + t + 4) * 136 + wn + nj * 8 + g]);
                #pragma unroll
                for (int mi = 0; mi < 4; mi++) mma_tf32(acc[mi][nj], af[mi], bf);
            }
        }
        __syncthreads();
    }

    #pragma unroll
    for (int mi = 0; mi < 4; mi++) {
        #pragma unroll
        for (int nj = 0; nj < 4; nj++) {
            int c = n0 + wn + nj * 8 + 2 * t;
            int r0 = m0 + wm + mi * 16 + g;
            int r1 = r0 + 8;
            float2 o0 = {acc[mi][nj][0], acc[mi][nj][1]};
            float2 o1 = {acc[mi][nj][2], acc[mi][nj][3]};
            if (bias) {
                float2 bv = *(const float2*)(bias + c);
                o0.x += bv.x; o0.y += bv.y; o1.x += bv.x; o1.y += bv.y;
            }
            if (res) {
                float2 ra = *(const float2*)(res + (size_t)r0 * N + c);
                float2 rb = *(const float2*)(res + (size_t)r1 * N + c);
                o0.x += ra.x; o0.y += ra.y; o1.x += rb.x; o1.y += rb.y;
            }
            if (RELU) {
                o0.x = fmaxf(o0.x, 0.f); o0.y = fmaxf(o0.y, 0.f);
                o1.x = fmaxf(o1.x, 0.f); o1.y = fmaxf(o1.y, 0.f);
            }
            *(float2*)(C + (size_t)r0 * N + c) = o0;
            *(float2*)(C + (size_t)r1 * N + c) = o1;
        }
    }
}

// ============================================================
// Merged QKV GEMM: 2 heads per CTA, BN=128, 256 thr.
// Q,K written (b,h,t,d); V written TRANSPOSED (b,h,d,t).
// ============================================================
__global__ __launch_bounds__(256) void qkv_mma2(
    const float* __restrict__ h, const float* __restrict__ wq,
    const float* __restrict__ wk, const float* __restrict__ wv,
    float* __restrict__ q, float* __restrict__ k, float* __restrict__ v) {
    extern __shared__ float smx[];
    float* Bsm = smx + 2 * G_ASTG;
    uint32_t sA = (uint32_t)__cvta_generic_to_shared(smx);
    uint32_t sB = (uint32_t)__cvta_generic_to_shared(Bsm);

    int which = blockIdx.y >> 3;          // 0,1,2
    int hp = blockIdx.y & 7;              // head pair: heads 2hp, 2hp+1
    const float* Wb = (which == 0 ? wq : (which == 1 ? wk : wv));
    float* O = (which == 0 ? q : (which == 1 ? k : v));

    int tid = threadIdx.x;
    int warp = tid >> 5, lane = tid & 31;
    int g = lane >> 2, t = lane & 3;
    int tile = lane >> 3, rl = lane & 7;
    int wm = (warp >> 2) * 64, wn = (warp & 3) * 32;
    int m0 = blockIdx.x * 128;

    float acc[4][4][4] = {};
    int a_rbase = wm + (tile & 1) * 8 + rl;
    int a_sbase = (tile >> 1);

    auto pre = [&](int st, int k0) {
        #pragma unroll
        for (int i = 0; i < 4; i++) {
            int ch = tid + 256 * i;
            int r = ch >> 3, sg = ch & 7;
            cp16(sA + (uint32_t)(st * G_ASTG + r * 36 + sg * 4) * 4,
                 h + (size_t)(m0 + r) * CC + k0 + sg * 4);
        }
        #pragma unroll
        for (int i = 0; i < 4; i++) {
            int ch = tid + 256 * i;
            int r = ch >> 5, c = (ch & 31) * 4;     // c in [0,128), 4-aligned
            int head = 2 * hp + (c >> 6);
            cp16(sB + (uint32_t)(st * G_BSTG + r * 136 + c) * 4,
                 Wb + (size_t)head * CC * DD + (size_t)(k0 + r) * DD + (c & 63));
        }
        cp_commit();
    };

    pre(0, 0);
    int nk = CC >> 5;
    for (int kk = 0; kk < nk; kk++) {
        int st = kk & 1;
        if (kk + 1 < nk) { pre(st ^ 1, (kk + 1) << 5); cp_wait<1>(); }
        else cp_wait<0>();
        __syncthreads();

        const float* bsp = Bsm + st * G_BSTG;
        uint32_t sAs = sA + (uint32_t)(st * G_ASTG) * 4;
        #pragma unroll
        for (int ks = 0; ks < 4; ks++) {
            unsigned af[4][4];
            #pragma unroll
            for (int mi = 0; mi < 4; mi++) {
                ldsm4(af[mi][0], af[mi][1], af[mi][2], af[mi][3],
                      sAs + (uint32_t)((a_rbase + mi * 16) * 36 + (2 * ks + a_sbase) * 4) * 4);
            }
            #pragma unroll
            for (int nj = 0; nj < 4; nj++) {
                unsigned bf[2];
                bf[0] = __float_as_uint(bsp[(ks * 8 + t) * 136 + wn + nj * 8 + g]);
                bf[1] = __float_as_uint(bsp[(ks * 8 + t + 4) * 136 + wn + nj * 8 + g]);
                #pragma unroll
                for (int mi = 0; mi < 4; mi++) mma_tf32(acc[mi][nj], af[mi], bf);
            }
        }
        __syncthreads();
    }

    #pragma unroll
    for (int mi = 0; mi < 4; mi++) {
        #pragma unroll
        for (int nj = 0; nj < 4; nj++) {
            int c = wn + nj * 8 + 2 * t;          // [0,128), even
            int head = 2 * hp + (c >> 6);
            int d = c & 63;
            int m0r = m0 + wm + mi * 16 + g;
            int m1r = m0r + 8;
            int b0 = m0r >> 11, t0i = m0r & (TT - 1);
            int b1 = m1r >> 11, t1i = m1r & (TT - 1);
            if (which == 2) {
                // V transposed: (b,h,d,t)
                size_t base0 = ((size_t)(b0 * HH + head) * DD);
                size_t base1 = ((size_t)(b1 * HH + head) * DD);
                O[(base0 + d)     * TT + t0i] = acc[mi][nj][0];
                O[(base0 + d + 1) * TT + t0i] = acc[mi][nj][1];
                O[(base1 + d)     * TT + t1i] = acc[mi][nj][2];
                O[(base1 + d + 1) * TT + t1i] = acc[mi][nj][3];
            } else {
                float2 o0 = {acc[mi][nj][0], acc[mi][nj][1]};
                float2 o1 = {acc[mi][nj][2], acc[mi][nj][3]};
                *(float2*)(O + (((size_t)(b0 * HH + head) * TT + t0i) << 6) + d) = o0;
                *(float2*)(O + (((size_t)(b1 * HH + head) * TT + t1i) << 6) + d) = o1;
            }
        }
    }
}

// ============================================================
// Flash attention. Br=64, Bc=64, 128 thr (4 warps).
// K AND V both staged via cp.async (V pre-transposed globally;
// XOR-seg swizzle applied to cp.async destination). P aliases Ks.
// Longest CTAs scheduled first (reversed t0).
// ============================================================
__global__ __launch_bounds__(128) void attn_mma(
    const float* __restrict__ Q, const float* __restrict__ K,
    const float* __restrict__ V, float* __restrict__ out) {
    __shared__ float Ks[64 * 68];   // K tile (key-major) / aliased P tile
    __shared__ float Vt[64 * 68];   // V^T tile [d][key], seg-swizzled

    int bh = blockIdx.y;
    int t0 = (int)(gridDim.x - 1 - blockIdx.x) * 64;   // longest-first
    const float* Qp = Q + (size_t)bh * TT * DD;
    const float* Kp = K + (size_t)bh * TT * DD;
    const float* Vp = V + (size_t)bh * TT * DD;        // (d, t) layout
    uint32_t sK = (uint32_t)__cvta_generic_to_shared(Ks);
    uint32_t sV = (uint32_t)__cvta_generic_to_shared(Vt);

    int tid = threadIdx.x;
    int warp = tid >> 5, lane = tid & 31;
    int g = lane >> 2, t = lane & 3;
    int tile = lane >> 3, rl = lane & 7;
    int wr = warp * 16;

    // stage Q (scaled, RNA tf32) into Ks, pull A-frags via ldmatrix
    #pragma unroll
    for (int i = 0; i < 8; i++) {
        int idx = tid + 128 * i;
        int r = idx >> 4, c4 = (idx & 15) * 4;
        float4 qv = *(const float4*)(Qp + (size_t)(t0 + r) * DD + c4);
        uint4 u = {f2tf(qv.x * 0.125f), f2tf(qv.y * 0.125f),
                   f2tf(qv.z * 0.125f), f2tf(qv.w * 0.125f)};
        *(uint4*)&Ks[r * 68 + c4] = u;
    }
    __syncthreads();
    unsigned qa[8][4];
    {
        int row = wr + (tile & 1) * 8 + rl;
        #pragma unroll
        for (int ks = 0; ks < 8; ks++)
            ldsm4(qa[ks][0], qa[ks][1], qa[ks][2], qa[ks][3],
                  sK + (uint32_t)(row * 68 + (2 * ks + (tile >> 1)) * 4) * 4);
    }
    __syncthreads();

    float m0r = -1e30f, m1r = -1e30f, l0 = 0.f, l1 = 0.f;
    float oacc[8][4] = {};

    int ntiles = t0 / 64 + 1;
    for (int it = 0; it < ntiles; it++) {
        int s0 = it * 64;
        // K via cp.async (key-major)
        #pragma unroll
        for (int i = 0; i < 8; i++) {
            int ch = tid + 128 * i;
            int r = ch >> 4, sg = ch & 15;
            cp16(sK + (uint32_t)(r * 68 + sg * 4) * 4,
                 Kp + (size_t)(s0 + r) * DD + sg * 4);
        }
        // V via cp.async (d-major, swizzled destination)
        #pragma unroll
        for (int i = 0; i < 8; i++) {
            int ch = tid + 128 * i;
            int d = ch >> 4, sg = ch & 15;
            int pc = (sg ^ ((d >> 2) & 15)) * 4;
            cp16(sV + (uint32_t)(d * 68 + pc) * 4,
                 Vp + (size_t)d * TT + s0 + sg * 4);
        }
        cp_commit();
        cp_wait<0>();
        __syncthreads();

        // S = Q @ K^T
        float sacc[8][4] = {};
        #pragma unroll
        for (int ks = 0; ks < 8; ks++) {
            #pragma unroll
            for (int nj2 = 0; nj2 < 4; nj2++) {
                unsigned r0, r1, r2, r3;
                int row = nj2 * 16 + (tile >> 1) * 8 + rl;
                int seg = 2 * ks + (tile & 1);
                ldsm4(r0, r1, r2, r3, sK + (uint32_t)(row * 68 + seg * 4) * 4);
                unsigned b0[2] = {r0, r1}, b1[2] = {r2, r3};
                mma_tf32(sacc[2 * nj2], qa[ks], b0);
                mma_tf32(sacc[2 * nj2 + 1], qa[ks], b1);
            }
        }
        __syncthreads();   // Ks reads done before P overwrite

        // causal mask (diagonal tile only)
        if (s0 == t0) {
            #pragma unroll
            for (int nj = 0; nj < 8; nj++) {
                int c0 = nj * 8 + 2 * t, c1 = c0 + 1;
                int r0 = wr + g, r1 = r0 + 8;
                if (c0 > r0) sacc[nj][0] = -1e30f;
                if (c1 > r0) sacc[nj][1] = -1e30f;
                if (c0 > r1) sacc[nj][2] = -1e30f;
                if (c1 > r1) sacc[nj][3] = -1e30f;
            }
        }

        // online softmax
        float mt0 = -1e30f, mt1 = -1e30f;
        #pragma unroll
        for (int nj = 0; nj < 8; nj++) {
            mt0 = fmaxf(mt0, fmaxf(sacc[nj][0], sacc[nj][1]));
            mt1 = fmaxf(mt1, fmaxf(sacc[nj][2], sacc[nj][3]));
        }
        #pragma unroll
        for (int o = 1; o <= 2; o <<= 1) {
            mt0 = fmaxf(mt0, __shfl_xor_sync(0xffffffffu, mt0, o));
            mt1 = fmaxf(mt1, __shfl_xor_sync(0xffffffffu, mt1, o));
        }
        float mn0 = fmaxf(m0r, mt0), mn1 = fmaxf(m1r, mt1);
        float sc0 = __expf(m0r - mn0), sc1 = __expf(m1r - mn1);
        float sum0 = 0.f, sum1 = 0.f;
        #pragma unroll
        for (int nj = 0; nj < 8; nj++) {
            float p00 = __expf(sacc[nj][0] - mn0);
            float p01 = __expf(sacc[nj][1] - mn0);
            float p10 = __expf(sacc[nj][2] - mn1);
            float p11 = __expf(sacc[nj][3] - mn1);
            sum0 += p00 + p01; sum1 += p10 + p11;
            int c = nj * 8 + 2 * t;
            Ks[(wr + g) * 68 + c] = p00;     Ks[(wr + g) * 68 + c + 1] = p01;
            Ks[(wr + 8 + g) * 68 + c] = p10; Ks[(wr + 8 + g) * 68 + c + 1] = p11;
        }
        #pragma unroll
        for (int o = 1; o <= 2; o <<= 1) {
            sum0 += __shfl_xor_sync(0xffffffffu, sum0, o);
            sum1 += __shfl_xor_sync(0xffffffffu, sum1, o);
        }
        l0 = l0 * sc0 + sum0;
        l1 = l1 * sc1 + sum1;
        m0r = mn0; m1r = mn1;
        #pragma unroll
        for (int nj = 0; nj < 8; nj++) {
            oacc[nj][0] *= sc0; oacc[nj][1] *= sc0;
            oacc[nj][2] *= sc1; oacc[nj][3] *= sc1;
        }
        __syncthreads();   // P visible to all warps

        // O += P @ V
        #pragma unroll
        for (int j = 0; j < 8; j++) {
            unsigned pa[4];
            {
                int row = wr + (tile & 1) * 8 + rl;
                int seg = 2 * j + (tile >> 1);
                ldsm4(pa[0], pa[1], pa[2], pa[3],
                      sK + (uint32_t)(row * 68 + seg * 4) * 4);
            }
            #pragma unroll
            for (int nj2 = 0; nj2 < 4; nj2++) {
                unsigned r0, r1, r2, r3;
                int row = nj2 * 16 + (tile >> 1) * 8 + rl;
                int lsg = 2 * j + (tile & 1);
                int psg = lsg ^ ((row >> 2) & 15);
                ldsm4(r0, r1, r2, r3, sV + (uint32_t)(row * 68 + psg * 4) * 4);
                unsigned b0[2] = {r0, r1}, b1[2] = {r2, r3};
                mma_tf32(oacc[2 * nj2], pa, b0);
                mma_tf32(oacc[2 * nj2 + 1], pa, b1);
            }
        }
        __syncthreads();
    }

    float inv0 = 1.f / l0, inv1 = 1.f / l1;
    int b = bh >> 4, hh = bh & 15;
    int tr0 = t0 + wr + g, tr1 = tr0 + 8;
    #pragma unroll
    for (int nj = 0; nj < 8; nj++) {
        int c = hh * DD + nj * 8 + 2 * t;
        float2 o0 = {oacc[nj][0] * inv0, oacc[nj][1] * inv0};
        float2 o1 = {oacc[nj][2] * inv1, oacc[nj][3] * inv1};
        *(float2*)(out + (size_t)(b * TT + tr0) * CC + c) = o0;
        *(float2*)(out + (size_t)(b * TT + tr1) * CC + c) = o1;
    }
}

// ============================================================
// launch
// ============================================================
extern "C" void kernel_launch(void* const* d_in, const int* in_sizes, int n_in,
                              void* d_out, int out_size) {
    const float* x      = (const float*)d_in[0];
    const float* wq     = (const float*)d_in[1];
    const float* wk     = (const float*)d_in[2];
    const float* wv     = (const float*)d_in[3];
    const float* w_proj = (const float*)d_in[4];
    const float* b_proj = (const float*)d_in[5];
    const float* w1     = (const float*)d_in[6];
    const float* b1     = (const float*)d_in[7];
    const float* w2     = (const float*)d_in[8];
    const float* b2     = (const float*)d_in[9];
    const float* g1     = (const float*)d_in[10];
    const float* be1    = (const float*)d_in[11];
    const float* g2     = (const float*)d_in[12];
    const float* be2    = (const float*)d_in[13];
    float* out = (float*)d_out;

    float *h1, *q, *k, *v, *attn, *x1, *h2, *ff1;
    cudaGetSymbolAddress((void**)&h1, g_h1);
    cudaGetSymbolAddress((void**)&q, g_q);
    cudaGetSymbolAddress((void**)&k, g_k);
    cudaGetSymbolAddress((void**)&v, g_v);
    cudaGetSymbolAddress((void**)&attn, g_attn);
    cudaGetSymbolAddress((void**)&x1, g_x1);
    cudaGetSymbolAddress((void**)&h2, g_h2);
    cudaGetSymbolAddress((void**)&ff1, g_ff1);

    cudaFuncSetAttribute(gemm_mma<false>, cudaFuncAttributeMaxDynamicSharedMemorySize, G_SMEM);
    cudaFuncSetAttribute(gemm_mma<true>,  cudaFuncAttributeMaxDynamicSharedMemorySize, G_SMEM);
    cudaFuncSetAttribute(qkv_mma2, cudaFuncAttributeMaxDynamicSharedMemorySize, G_SMEM);

    // 1. LN1
    ln_kernel<<<MTOT, 256>>>(x, g1, be1, h1);
    // 2. QKV (merged; V written transposed)
    qkv_mma2<<<dim3(MTOT / 128, 3 * (HH / 2)), 256, G_SMEM>>>(h1, wq, wk, wv, q, k, v);
    // 3. attention
    attn_mma<<<dim3(TT / 64, BBATCH * HH), 128>>>(q, k, v, attn);
    // 4. proj + bias + residual -> x1
    gemm_mma<false><<<dim3(CC / 128, MTOT / 128), 256, G_SMEM>>>(attn, w_proj, b_proj, x, x1,
                                                                 MTOT, CC, CC);
    // 5. LN2
    ln_kernel<<<MTOT, 256>>>(x1, g2, be2, h2);
    // 6. FF1 + bias + relu
    gemm_mma<true><<<dim3(FFDIM / 128, MTOT / 128), 256, G_SMEM>>>(h2, w1, b1, nullptr, ff1,
                                                                   MTOT, FFDIM, CC);
    // 7. FF2 + bias + residual -> out
    gemm_mma<false><<<dim3(CC / 128, MTOT / 128), 256, G_SMEM>>>(ff1, w2, b2, x1, out,
                                                                 MTOT, CC, FFDIM);
}

// round 10
// speedup vs baseline: 1.2093x; 1.0085x over previous
#include <cuda_runtime.h>
#include <math.h>
#include <stdint.h>

#define TT 2048
#define CC 1024
#define HH 16
#define DD 64
#define BBATCH 2
#define MTOT (BBATCH * TT)   // 4096
#define FFDIM (4 * CC)       // 4096

// -------- scratch (alloc-free) --------
__device__ float g_h1[MTOT * CC];
__device__ float g_q[MTOT * CC];     // (b,h,t,d)
__device__ float g_k[MTOT * CC];     // (b,h,t,d)
__device__ float g_v[MTOT * CC];     // (b,h,d,t) transposed
__device__ float g_attn[MTOT * CC];
__device__ float g_x1[MTOT * CC];
__device__ float g_h2[MTOT * CC];
__device__ float g_ff1[MTOT * FFDIM];
// transposed weights [N][K]
__device__ float g_wpt[CC * CC];
__device__ float g_w1t[FFDIM * CC];
__device__ float g_w2t[CC * FFDIM];
__device__ float g_wqt[HH * DD * CC];
__device__ float g_wkt[HH * DD * CC];
__device__ float g_wvt[HH * DD * CC];

// -------- helpers --------
__device__ __forceinline__ unsigned f2tf(float f) {
    unsigned u;
    asm("cvt.rna.tf32.f32 %0, %1;" : "=r"(u) : "f"(f));
    return u;
}
__device__ __forceinline__ void mma_tf32(float* c, const unsigned* a, const unsigned* b) {
    asm volatile(
        "mma.sync.aligned.m16n8k8.row.col.f32.tf32.tf32.f32 "
        "{%0,%1,%2,%3}, {%4,%5,%6,%7}, {%8,%9}, {%0,%1,%2,%3};"
        : "+f"(c[0]), "+f"(c[1]), "+f"(c[2]), "+f"(c[3])
        : "r"(a[0]), "r"(a[1]), "r"(a[2]), "r"(a[3]), "r"(b[0]), "r"(b[1]));
}
__device__ __forceinline__ void cp16(uint32_t s, const void* g) {
    asm volatile("cp.async.ca.shared.global [%0], [%1], 16;" :: "r"(s), "l"(g));
}
__device__ __forceinline__ void cp_commit() { asm volatile("cp.async.commit_group;"); }
template <int N>
__device__ __forceinline__ void cp_wait() { asm volatile("cp.async.wait_group %0;" :: "n"(N)); }
__device__ __forceinline__ void ldsm4(unsigned& r0, unsigned& r1, unsigned& r2, unsigned& r3,
                                      uint32_t a) {
    asm volatile("ldmatrix.sync.aligned.m8n8.x4.shared.b16 {%0,%1,%2,%3}, [%4];"
                 : "=r"(r0), "=r"(r1), "=r"(r2), "=r"(r3) : "r"(a));
}

// ============================================================
// Batched transpose: in[b][R][C] -> out[b][C][R]
// ============================================================
__global__ void transpose_w(const float* __restrict__ in, float* __restrict__ out,
                            int R, int Cc) {
    __shared__ float t[32][33];
    const float* ip = in + (size_t)blockIdx.z * R * Cc;
    float* op = out + (size_t)blockIdx.z * R * Cc;
    int c0 = blockIdx.x * 32, r0 = blockIdx.y * 32;
    int x = threadIdx.x, y = threadIdx.y;
    #pragma unroll
    for (int i = 0; i < 32; i += 8)
        t[y + i][x] = ip[(size_t)(r0 + y + i) * Cc + c0 + x];
    __syncthreads();
    #pragma unroll
    for (int i = 0; i < 32; i += 8)
        op[(size_t)(c0 + y + i) * R + r0 + x] = t[x][y + i];
}

// ============================================================
// LayerNorm: one block (256 thr) per row of 1024
// ============================================================
__global__ void ln_kernel(const float* __restrict__ x, const float* __restrict__ g,
                          const float* __restrict__ b, float* __restrict__ out) {
    __shared__ float red[8];
    __shared__ float s_mu, s_rstd;
    int row = blockIdx.x;
    int tid = threadIdx.x;
    const float* xr = x + (size_t)row * CC;

    float v0 = xr[tid], v1 = xr[tid + 256], v2 = xr[tid + 512], v3 = xr[tid + 768];
    float s = v0 + v1 + v2 + v3;
    #pragma unroll
    for (int o = 16; o > 0; o >>= 1) s += __shfl_xor_sync(0xffffffffu, s, o);
    if ((tid & 31) == 0) red[tid >> 5] = s;
    __syncthreads();
    if (tid == 0) {
        float t = 0.f;
        #pragma unroll
        for (int i = 0; i < 8; i++) t += red[i];
        s_mu = t * (1.0f / CC);
    }
    __syncthreads();
    float mu = s_mu;
    float d0 = v0 - mu, d1 = v1 - mu, d2 = v2 - mu, d3 = v3 - mu;
    float s2 = d0 * d0 + d1 * d1 + d2 * d2 + d3 * d3;
    #pragma unroll
    for (int o = 16; o > 0; o >>= 1) s2 += __shfl_xor_sync(0xffffffffu, s2, o);
    __syncthreads();
    if ((tid & 31) == 0) red[tid >> 5] = s2;
    __syncthreads();
    if (tid == 0) {
        float t = 0.f;
        #pragma unroll
        for (int i = 0; i < 8; i++) t += red[i];
        s_rstd = rsqrtf(t * (1.0f / CC) + 1e-5f);
    }
    __syncthreads();
    float rstd = s_rstd;
    float* orow = out + (size_t)row * CC;
    orow[tid]       = d0 * rstd * g[tid]       + b[tid];
    orow[tid + 256] = d1 * rstd * g[tid + 256] + b[tid + 256];
    orow[tid + 512] = d2 * rstd * g[tid + 512] + b[tid + 512];
    orow[tid + 768] = d3 * rstd * g[tid + 768] + b[tid + 768];
}

// ============================================================
// tf32 GEMM, both operands via ldmatrix. C = A(MxK) @ Bt^T.
// A [M][K] row-major; Bt [N][K] row-major (n-major tile).
// BM=BN=128, BK=32, 256 thr = 8 warps (2x4), warp tile 64x32.
// Both smem tiles 128x36 (pitch-36, conflict-free ldsm4).
// ============================================================
#define G_TSTG (128 * 36)
#define G_SMEM ((4 * G_TSTG) * 4)   // 2 stages x (A+B) = 73728 B

template <bool RELU>
__global__ __launch_bounds__(256) void gemm_mma(
    const float* __restrict__ A, const float* __restrict__ Bt,
    const float* __restrict__ bias, const float* __restrict__ res,
    float* __restrict__ C, int M, int N, int K) {
    extern __shared__ float smx[];
    uint32_t sA = (uint32_t)__cvta_generic_to_shared(smx);
    uint32_t sB = sA + 2 * G_TSTG * 4;

    int tid = threadIdx.x;
    int warp = tid >> 5, lane = tid & 31;
    int g = lane >> 2, t = lane & 3;
    int tile = lane >> 3, rl = lane & 7;
    int wm = (warp >> 2) * 64, wn = (warp & 3) * 32;
    int m0 = blockIdx.y * 128, n0 = blockIdx.x * 128;

    float acc[4][4][4] = {};
    int a_rbase = wm + (tile & 1) * 8 + rl;
    int a_sbase = (tile >> 1);
    int b_rbase = wn + (tile >> 1) * 8 + rl;
    int b_sbase = (tile & 1);

    auto pre = [&](int st, int k0) {
        #pragma unroll
        for (int i = 0; i < 4; i++) {
            int ch = tid + 256 * i;
            int r = ch >> 3, sg = ch & 7;
            cp16(sA + (uint32_t)(st * G_TSTG + r * 36 + sg * 4) * 4,
                 A + (size_t)(m0 + r) * K + k0 + sg * 4);
        }
        #pragma unroll
        for (int i = 0; i < 4; i++) {
            int ch = tid + 256 * i;
            int r = ch >> 3, sg = ch & 7;
            cp16(sB + (uint32_t)(st * G_TSTG + r * 36 + sg * 4) * 4,
                 Bt + (size_t)(n0 + r) * K + k0 + sg * 4);
        }
        cp_commit();
    };

    pre(0, 0);
    int nk = K >> 5;
    for (int kk = 0; kk < nk; kk++) {
        int st = kk & 1;
        if (kk + 1 < nk) { pre(st ^ 1, (kk + 1) << 5); cp_wait<1>(); }
        else cp_wait<0>();
        __syncthreads();

        uint32_t sAs = sA + (uint32_t)(st * G_TSTG) * 4;
        uint32_t sBs = sB + (uint32_t)(st * G_TSTG) * 4;
        #pragma unroll
        for (int ks = 0; ks < 4; ks++) {
            unsigned af[4][4];
            #pragma unroll
            for (int mi = 0; mi < 4; mi++) {
                ldsm4(af[mi][0], af[mi][1], af[mi][2], af[mi][3],
                      sAs + (uint32_t)((a_rbase + mi * 16) * 36 + (2 * ks + a_sbase) * 4) * 4);
            }
            #pragma unroll
            for (int nj2 = 0; nj2 < 2; nj2++) {
                unsigned r0, r1, r2, r3;
                ldsm4(r0, r1, r2, r3,
                      sBs + (uint32_t)((b_rbase + nj2 * 16) * 36 + (2 * ks + b_sbase) * 4) * 4);
                unsigned b0[2] = {r0, r1}, b1[2] = {r2, r3};
                #pragma unroll
                for (int mi = 0; mi < 4; mi++) {
                    mma_tf32(acc[mi][2 * nj2],     af[mi], b0);
                    mma_tf32(acc[mi][2 * nj2 + 1], af[mi], b1);
                }
            }
        }
        __syncthreads();
    }

    #pragma unroll
    for (int mi = 0; mi < 4; mi++) {
        #pragma unroll
        for (int nj = 0; nj < 4; nj++) {
            int c = n0 + wn + nj * 8 + 2 * t;
            int r0 = m0 + wm + mi * 16 + g;
            int r1 = r0 + 8;
            float2 o0 = {acc[mi][nj][0], acc[mi][nj][1]};
            float2 o1 = {acc[mi][nj][2], acc[mi][nj][3]};
            if (bias) {
                float2 bv = *(const float2*)(bias + c);
                o0.x += bv.x; o0.y += bv.y; o1.x += bv.x; o1.y += bv.y;
            }
            if (res) {
                float2 ra = *(const float2*)(res + (size_t)r0 * N + c);
                float2 rb = *(const float2*)(res + (size_t)r1 * N + c);
                o0.x += ra.x; o0.y += ra.y; o1.x += rb.x; o1.y += rb.y;
            }
            if (RELU) {
                o0.x = fmaxf(o0.x, 0.f); o0.y = fmaxf(o0.y, 0.f);
                o1.x = fmaxf(o1.x, 0.f); o1.y = fmaxf(o1.y, 0.f);
            }
            *(float2*)(C + (size_t)r0 * N + c) = o0;
            *(float2*)(C + (size_t)r1 * N + c) = o1;
        }
    }
}

// ============================================================
// Merged QKV GEMM: 2 heads per CTA, both operands via ldmatrix.
// Weights pre-transposed: Wt[h][d][K]. B tile rows = hp*128 + n.
// Q,K out (b,h,t,d); V out transposed (b,h,d,t).
// ============================================================
__global__ __launch_bounds__(256) void qkv_mma2(
    const float* __restrict__ h, const float* __restrict__ wqt,
    const float* __restrict__ wkt, const float* __restrict__ wvt,
    float* __restrict__ q, float* __restrict__ k, float* __restrict__ v) {
    extern __shared__ float smx[];
    uint32_t sA = (uint32_t)__cvta_generic_to_shared(smx);
    uint32_t sB = sA + 2 * G_TSTG * 4;

    int which = blockIdx.y >> 3;
    int hp = blockIdx.y & 7;
    const float* Wt = (which == 0 ? wqt : (which == 1 ? wkt : wvt));
    float* O = (which == 0 ? q : (which == 1 ? k : v));

    int tid = threadIdx.x;
    int warp = tid >> 5, lane = tid & 31;
    int g = lane >> 2, t = lane & 3;
    int tile = lane >> 3, rl = lane & 7;
    int wm = (warp >> 2) * 64, wn = (warp & 3) * 32;
    int m0 = blockIdx.x * 128;

    float acc[4][4][4] = {};
    int a_rbase = wm + (tile & 1) * 8 + rl;
    int a_sbase = (tile >> 1);
    int b_rbase = wn + (tile >> 1) * 8 + rl;
    int b_sbase = (tile & 1);

    auto pre = [&](int st, int k0) {
        #pragma unroll
        for (int i = 0; i < 4; i++) {
            int ch = tid + 256 * i;
            int r = ch >> 3, sg = ch & 7;
            cp16(sA + (uint32_t)(st * G_TSTG + r * 36 + sg * 4) * 4,
                 h + (size_t)(m0 + r) * CC + k0 + sg * 4);
        }
        #pragma unroll
        for (int i = 0; i < 4; i++) {
            int ch = tid + 256 * i;
            int r = ch >> 3, sg = ch & 7;   // r = local n row (2 heads span)
            cp16(sB + (uint32_t)(st * G_TSTG + r * 36 + sg * 4) * 4,
                 Wt + (size_t)(hp * 128 + r) * CC + k0 + sg * 4);
        }
        cp_commit();
    };

    pre(0, 0);
    int nk = CC >> 5;
    for (int kk = 0; kk < nk; kk++) {
        int st = kk & 1;
        if (kk + 1 < nk) { pre(st ^ 1, (kk + 1) << 5); cp_wait<1>(); }
        else cp_wait<0>();
        __syncthreads();

        uint32_t sAs = sA + (uint32_t)(st * G_TSTG) * 4;
        uint32_t sBs = sB + (uint32_t)(st * G_TSTG) * 4;
        #pragma unroll
        for (int ks = 0; ks < 4; ks++) {
            unsigned af[4][4];
            #pragma unroll
            for (int mi = 0; mi < 4; mi++) {
                ldsm4(af[mi][0], af[mi][1], af[mi][2], af[mi][3],
                      sAs + (uint32_t)((a_rbase + mi * 16) * 36 + (2 * ks + a_sbase) * 4) * 4);
            }
            #pragma unroll
            for (int nj2 = 0; nj2 < 2; nj2++) {
                unsigned r0, r1, r2, r3;
                ldsm4(r0, r1, r2, r3,
                      sBs + (uint32_t)((b_rbase + nj2 * 16) * 36 + (2 * ks + b_sbase) * 4) * 4);
                unsigned b0[2] = {r0, r1}, b1[2] = {r2, r3};
                #pragma unroll
                for (int mi = 0; mi < 4; mi++) {
                    mma_tf32(acc[mi][2 * nj2],     af[mi], b0);
                    mma_tf32(acc[mi][2 * nj2 + 1], af[mi], b1);
                }
            }
        }
        __syncthreads();
    }

    #pragma unroll
    for (int mi = 0; mi < 4; mi++) {
        #pragma unroll
        for (int nj = 0; nj < 4; nj++) {
            int c = wn + nj * 8 + 2 * t;
            int head = 2 * hp + (c >> 6);
            int d = c & 63;
            int m0r = m0 + wm + mi * 16 + g;
            int m1r = m0r + 8;
            int b0 = m0r >> 11, t0i = m0r & (TT - 1);
            int b1 = m1r >> 11, t1i = m1r & (TT - 1);
            if (which == 2) {
                size_t base0 = ((size_t)(b0 * HH + head) * DD);
                size_t base1 = ((size_t)(b1 * HH + head) * DD);
                O[(base0 + d)     * TT + t0i] = acc[mi][nj][0];
                O[(base0 + d + 1) * TT + t0i] = acc[mi][nj][1];
                O[(base1 + d)     * TT + t1i] = acc[mi][nj][2];
                O[(base1 + d + 1) * TT + t1i] = acc[mi][nj][3];
            } else {
                float2 o0 = {acc[mi][nj][0], acc[mi][nj][1]};
                float2 o1 = {acc[mi][nj][2], acc[mi][nj][3]};
                *(float2*)(O + (((size_t)(b0 * HH + head) * TT + t0i) << 6) + d) = o0;
                *(float2*)(O + (((size_t)(b1 * HH + head) * TT + t1i) << 6) + d) = o1;
            }
        }
    }
}

// ============================================================
// Flash attention (unchanged from round 8)
// ============================================================
__global__ __launch_bounds__(128) void attn_mma(
    const float* __restrict__ Q, const float* __restrict__ K,
    const float* __restrict__ V, float* __restrict__ out) {
    __shared__ float Ks[64 * 68];
    __shared__ float Vt[64 * 68];

    int bh = blockIdx.y;
    int t0 = (int)(gridDim.x - 1 - blockIdx.x) * 64;
    const float* Qp = Q + (size_t)bh * TT * DD;
    const float* Kp = K + (size_t)bh * TT * DD;
    const float* Vp = V + (size_t)bh * TT * DD;
    uint32_t sK = (uint32_t)__cvta_generic_to_shared(Ks);
    uint32_t sV = (uint32_t)__cvta_generic_to_shared(Vt);

    int tid = threadIdx.x;
    int warp = tid >> 5, lane = tid & 31;
    int g = lane >> 2, t = lane & 3;
    int tile = lane >> 3, rl = lane & 7;
    int wr = warp * 16;

    #pragma unroll
    for (int i = 0; i < 8; i++) {
        int idx = tid + 128 * i;
        int r = idx >> 4, c4 = (idx & 15) * 4;
        float4 qv = *(const float4*)(Qp + (size_t)(t0 + r) * DD + c4);
        uint4 u = {f2tf(qv.x * 0.125f), f2tf(qv.y * 0.125f),
                   f2tf(qv.z * 0.125f), f2tf(qv.w * 0.125f)};
        *(uint4*)&Ks[r * 68 + c4] = u;
    }
    __syncthreads();
    unsigned qa[8][4];
    {
        int row = wr + (tile & 1) * 8 + rl;
        #pragma unroll
        for (int ks = 0; ks < 8; ks++)
            ldsm4(qa[ks][0], qa[ks][1], qa[ks][2], qa[ks][3],
                  sK + (uint32_t)(row * 68 + (2 * ks + (tile >> 1)) * 4) * 4);
    }
    __syncthreads();

    float m0r = -1e30f, m1r = -1e30f, l0 = 0.f, l1 = 0.f;
    float oacc[8][4] = {};

    int ntiles = t0 / 64 + 1;
    for (int it = 0; it < ntiles; it++) {
        int s0 = it * 64;
        #pragma unroll
        for (int i = 0; i < 8; i++) {
            int ch = tid + 128 * i;
            int r = ch >> 4, sg = ch & 15;
            cp16(sK + (uint32_t)(r * 68 + sg * 4) * 4,
                 Kp + (size_t)(s0 + r) * DD + sg * 4);
        }
        #pragma unroll
        for (int i = 0; i < 8; i++) {
            int ch = tid + 128 * i;
            int d = ch >> 4, sg = ch & 15;
            int pc = (sg ^ ((d >> 2) & 15)) * 4;
            cp16(sV + (uint32_t)(d * 68 + pc) * 4,
                 Vp + (size_t)d * TT + s0 + sg * 4);
        }
        cp_commit();
        cp_wait<0>();
        __syncthreads();

        float sacc[8][4] = {};
        #pragma unroll
        for (int ks = 0; ks < 8; ks++) {
            #pragma unroll
            for (int nj2 = 0; nj2 < 4; nj2++) {
                unsigned r0, r1, r2, r3;
                int row = nj2 * 16 + (tile >> 1) * 8 + rl;
                int seg = 2 * ks + (tile & 1);
                ldsm4(r0, r1, r2, r3, sK + (uint32_t)(row * 68 + seg * 4) * 4);
                unsigned b0[2] = {r0, r1}, b1[2] = {r2, r3};
                mma_tf32(sacc[2 * nj2], qa[ks], b0);
                mma_tf32(sacc[2 * nj2 + 1], qa[ks], b1);
            }
        }
        __syncthreads();

        if (s0 == t0) {
            #pragma unroll
            for (int nj = 0; nj < 8; nj++) {
                int c0 = nj * 8 + 2 * t, c1 = c0 + 1;
                int r0 = wr + g, r1 = r0 + 8;
                if (c0 > r0) sacc[nj][0] = -1e30f;
                if (c1 > r0) sacc[nj][1] = -1e30f;
                if (c0 > r1) sacc[nj][2] = -1e30f;
                if (c1 > r1) sacc[nj][3] = -1e30f;
            }
        }

        float mt0 = -1e30f, mt1 = -1e30f;
        #pragma unroll
        for (int nj = 0; nj < 8; nj++) {
            mt0 = fmaxf(mt0, fmaxf(sacc[nj][0], sacc[nj][1]));
            mt1 = fmaxf(mt1, fmaxf(sacc[nj][2], sacc[nj][3]));
        }
        #pragma unroll
        for (int o = 1; o <= 2; o <<= 1) {
            mt0 = fmaxf(mt0, __shfl_xor_sync(0xffffffffu, mt0, o));
            mt1 = fmaxf(mt1, __shfl_xor_sync(0xffffffffu, mt1, o));
        }
        float mn0 = fmaxf(m0r, mt0), mn1 = fmaxf(m1r, mt1);
        float sc0 = __expf(m0r - mn0), sc1 = __expf(m1r - mn1);
        float sum0 = 0.f, sum1 = 0.f;
        #pragma unroll
        for (int nj = 0; nj < 8; nj++) {
            float p00 = __expf(sacc[nj][0] - mn0);
            float p01 = __expf(sacc[nj][1] - mn0);
            float p10 = __expf(sacc[nj][2] - mn1);
            float p11 = __expf(sacc[nj][3] - mn1);
            sum0 += p00 + p01; sum1 += p10 + p11;
            int c = nj * 8 + 2 * t;
            Ks[(wr + g) * 68 + c] = p00;     Ks[(wr + g) * 68 + c + 1] = p01;
            Ks[(wr + 8 + g) * 68 + c] = p10; Ks[(wr + 8 + g) * 68 + c + 1] = p11;
        }
        #pragma unroll
        for (int o = 1; o <= 2; o <<= 1) {
            sum0 += __shfl_xor_sync(0xffffffffu, sum0, o);
            sum1 += __shfl_xor_sync(0xffffffffu, sum1, o);
        }
        l0 = l0 * sc0 + sum0;
        l1 = l1 * sc1 + sum1;
        m0r = mn0; m1r = mn1;
        #pragma unroll
        for (int nj = 0; nj < 8; nj++) {
            oacc[nj][0] *= sc0; oacc[nj][1] *= sc0;
            oacc[nj][2] *= sc1; oacc[nj][3] *= sc1;
        }
        __syncthreads();

        #pragma unroll
        for (int j = 0; j < 8; j++) {
            unsigned pa[4];
            {
                int row = wr + (tile & 1) * 8 + rl;
                int seg = 2 * j + (tile >> 1);
                ldsm4(pa[0], pa[1], pa[2], pa[3],
                      sK + (uint32_t)(row * 68 + seg * 4) * 4);
            }
            #pragma unroll
            for (int nj2 = 0; nj2 < 4; nj2++) {
                unsigned r0, r1, r2, r3;
                int row = nj2 * 16 + (tile >> 1) * 8 + rl;
                int lsg = 2 * j + (tile & 1);
                int psg = lsg ^ ((row >> 2) & 15);
                ldsm4(r0, r1, r2, r3, sV + (uint32_t)(row * 68 + psg * 4) * 4);
                unsigned b0[2] = {r0, r1}, b1[2] = {r2, r3};
                mma_tf32(oacc[2 * nj2], pa, b0);
                mma_tf32(oacc[2 * nj2 + 1], pa, b1);
            }
        }
        __syncthreads();
    }

    float inv0 = 1.f / l0, inv1 = 1.f / l1;
    int b = bh >> 4, hh = bh & 15;
    int tr0 = t0 + wr + g, tr1 = tr0 + 8;
    #pragma unroll
    for (int nj = 0; nj < 8; nj++) {
        int c = hh * DD + nj * 8 + 2 * t;
        float2 o0 = {oacc[nj][0] * inv0, oacc[nj][1] * inv0};
        float2 o1 = {oacc[nj][2] * inv1, oacc[nj][3] * inv1};
        *(float2*)(out + (size_t)(b * TT + tr0) * CC + c) = o0;
        *(float2*)(out + (size_t)(b * TT + tr1) * CC + c) = o1;
    }
}

// ============================================================
// launch
// ============================================================
extern "C" void kernel_launch(void* const* d_in, const int* in_sizes, int n_in,
                              void* d_out, int out_size) {
    const float* x      = (const float*)d_in[0];
    const float* wq     = (const float*)d_in[1];
    const float* wk     = (const float*)d_in[2];
    const float* wv     = (const float*)d_in[3];
    const float* w_proj = (const float*)d_in[4];
    const float* b_proj = (const float*)d_in[5];
    const float* w1     = (const float*)d_in[6];
    const float* b1     = (const float*)d_in[7];
    const float* w2     = (const float*)d_in[8];
    const float* b2     = (const float*)d_in[9];
    const float* g1     = (const float*)d_in[10];
    const float* be1    = (const float*)d_in[11];
    const float* g2     = (const float*)d_in[12];
    const float* be2    = (const float*)d_in[13];
    float* out = (float*)d_out;

    float *h1, *q, *k, *v, *attn, *x1, *h2, *ff1;
    float *wpt, *w1t, *w2t, *wqt, *wkt, *wvt;
    cudaGetSymbolAddress((void**)&h1, g_h1);
    cudaGetSymbolAddress((void**)&q, g_q);
    cudaGetSymbolAddress((void**)&k, g_k);
    cudaGetSymbolAddress((void**)&v, g_v);
    cudaGetSymbolAddress((void**)&attn, g_attn);
    cudaGetSymbolAddress((void**)&x1, g_x1);
    cudaGetSymbolAddress((void**)&h2, g_h2);
    cudaGetSymbolAddress((void**)&ff1, g_ff1);
    cudaGetSymbolAddress((void**)&wpt, g_wpt);
    cudaGetSymbolAddress((void**)&w1t, g_w1t);
    cudaGetSymbolAddress((void**)&w2t, g_w2t);
    cudaGetSymbolAddress((void**)&wqt, g_wqt);
    cudaGetSymbolAddress((void**)&wkt, g_wkt);
    cudaGetSymbolAddress((void**)&wvt, g_wvt);

    cudaFuncSetAttribute(gemm_mma<false>, cudaFuncAttributeMaxDynamicSharedMemorySize, G_SMEM);
    cudaFuncSetAttribute(gemm_mma<true>,  cudaFuncAttributeMaxDynamicSharedMemorySize, G_SMEM);
    cudaFuncSetAttribute(qkv_mma2, cudaFuncAttributeMaxDynamicSharedMemorySize, G_SMEM);

    // 0. weight transposes -> [N][K]
    transpose_w<<<dim3(CC / 32, CC / 32, 1), dim3(32, 8)>>>(w_proj, wpt, CC, CC);
    transpose_w<<<dim3(FFDIM / 32, CC / 32, 1), dim3(32, 8)>>>(w1, w1t, CC, FFDIM);
    transpose_w<<<dim3(CC / 32, FFDIM / 32, 1), dim3(32, 8)>>>(w2, w2t, FFDIM, CC);
    transpose_w<<<dim3(DD / 32, CC / 32, HH), dim3(32, 8)>>>(wq, wqt, CC, DD);
    transpose_w<<<dim3(DD / 32, CC / 32, HH), dim3(32, 8)>>>(wk, wkt, CC, DD);
    transpose_w<<<dim3(DD / 32, CC / 32, HH), dim3(32, 8)>>>(wv, wvt, CC, DD);
    // 1. LN1
    ln_kernel<<<MTOT, 256>>>(x, g1, be1, h1);
    // 2. QKV (merged; V written transposed)
    qkv_mma2<<<dim3(MTOT / 128, 3 * (HH / 2)), 256, G_SMEM>>>(h1, wqt, wkt, wvt, q, k, v);
    // 3. attention
    attn_mma<<<dim3(TT / 64, BBATCH * HH), 128>>>(q, k, v, attn);
    // 4. proj + bias + residual -> x1
    gemm_mma<false><<<dim3(CC / 128, MTOT / 128), 256, G_SMEM>>>(attn, wpt, b_proj, x, x1,
                                                                 MTOT, CC, CC);
    // 5. LN2
    ln_kernel<<<MTOT, 256>>>(x1, g2, be2, h2);
    // 6. FF1 + bias + relu
    gemm_mma<true><<<dim3(FFDIM / 128, MTOT / 128), 256, G_SMEM>>>(h2, w1t, b1, nullptr, ff1,
                                                                   MTOT, FFDIM, CC);
    // 7. FF2 + bias + residual -> out
    gemm_mma<false><<<dim3(CC / 128, MTOT / 128), 256, G_SMEM>>>(ff1, w2t, b2, x1, out,
                                                                 MTOT, CC, FFDIM);
}

// round 11
// speedup vs baseline: 2.2682x; 1.8756x over previous
#include <cuda_runtime.h>
#include <cuda_fp16.h>
#include <math.h>
#include <stdint.h>

#define TT 2048
#define CC 1024
#define HH 16
#define DD 64
#define BBATCH 2
#define MTOT (BBATCH * TT)   // 4096
#define FFDIM (4 * CC)       // 4096

// -------- scratch (alloc-free) --------
__device__ __half g_h1[MTOT * CC];
__device__ __half g_q[MTOT * CC];     // (b,h,t,d), pre-scaled by 0.125
__device__ __half g_k[MTOT * CC];     // (b,h,t,d)
__device__ __half g_v[MTOT * CC];     // (b,h,d,t) transposed
__device__ __half g_attn[MTOT * CC];
__device__ float  g_x1[MTOT * CC];
__device__ __half g_h2[MTOT * CC];
__device__ __half g_ff1[MTOT * FFDIM];
// transposed fp16 weights [N][K]
__device__ __half g_wpt[CC * CC];
__device__ __half g_w1t[FFDIM * CC];
__device__ __half g_w2t[CC * FFDIM];
__device__ __half g_wqt[HH * DD * CC];
__device__ __half g_wkt[HH * DD * CC];
__device__ __half g_wvt[HH * DD * CC];

// -------- helpers --------
__device__ __forceinline__ void mma_f16(float* c, const unsigned* a, const unsigned* b) {
    asm volatile(
        "mma.sync.aligned.m16n8k16.row.col.f32.f16.f16.f32 "
        "{%0,%1,%2,%3}, {%4,%5,%6,%7}, {%8,%9}, {%0,%1,%2,%3};"
        : "+f"(c[0]), "+f"(c[1]), "+f"(c[2]), "+f"(c[3])
        : "r"(a[0]), "r"(a[1]), "r"(a[2]), "r"(a[3]), "r"(b[0]), "r"(b[1]));
}
__device__ __forceinline__ void cp16(uint32_t s, const void* g) {
    asm volatile("cp.async.ca.shared.global [%0], [%1], 16;" :: "r"(s), "l"(g));
}
__device__ __forceinline__ void cp_commit() { asm volatile("cp.async.commit_group;"); }
template <int N>
__device__ __forceinline__ void cp_wait() { asm volatile("cp.async.wait_group %0;" :: "n"(N)); }
__device__ __forceinline__ void ldsm4(unsigned& r0, unsigned& r1, unsigned& r2, unsigned& r3,
                                      uint32_t a) {
    asm volatile("ldmatrix.sync.aligned.m8n8.x4.shared.b16 {%0,%1,%2,%3}, [%4];"
                 : "=r"(r0), "=r"(r1), "=r"(r2), "=r"(r3) : "r"(a));
}
// tile: rows of 64 halves = 128B; seg (16B unit) swizzled by row&7 -> conflict-free
__device__ __forceinline__ uint32_t swz(uint32_t r, uint32_t seg) {
    return r * 128 + ((seg ^ (r & 7)) * 16);
}

// ============================================================
// Batched transpose fp32 -> fp16: in[b][R][C] -> out[b][C][R]
// ============================================================
__global__ void transpose_w(const float* __restrict__ in, __half* __restrict__ out,
                            int R, int Cc) {
    __shared__ float t[32][33];
    const float* ip = in + (size_t)blockIdx.z * R * Cc;
    __half* op = out + (size_t)blockIdx.z * R * Cc;
    int c0 = blockIdx.x * 32, r0 = blockIdx.y * 32;
    int x = threadIdx.x, y = threadIdx.y;
    #pragma unroll
    for (int i = 0; i < 32; i += 8)
        t[y + i][x] = ip[(size_t)(r0 + y + i) * Cc + c0 + x];
    __syncthreads();
    #pragma unroll
    for (int i = 0; i < 32; i += 8)
        op[(size_t)(c0 + y + i) * R + r0 + x] = __float2half(t[x][y + i]);
}

// ============================================================
// LayerNorm: fp32 in -> fp16 out
// ============================================================
__global__ void ln_kernel(const float* __restrict__ x, const float* __restrict__ g,
                          const float* __restrict__ b, __half* __restrict__ out) {
    __shared__ float red[8];
    __shared__ float s_mu, s_rstd;
    int row = blockIdx.x;
    int tid = threadIdx.x;
    const float* xr = x + (size_t)row * CC;

    float v0 = xr[tid], v1 = xr[tid + 256], v2 = xr[tid + 512], v3 = xr[tid + 768];
    float s = v0 + v1 + v2 + v3;
    #pragma unroll
    for (int o = 16; o > 0; o >>= 1) s += __shfl_xor_sync(0xffffffffu, s, o);
    if ((tid & 31) == 0) red[tid >> 5] = s;
    __syncthreads();
    if (tid == 0) {
        float t = 0.f;
        #pragma unroll
        for (int i = 0; i < 8; i++) t += red[i];
        s_mu = t * (1.0f / CC);
    }
    __syncthreads();
    float mu = s_mu;
    float d0 = v0 - mu, d1 = v1 - mu, d2 = v2 - mu, d3 = v3 - mu;
    float s2 = d0 * d0 + d1 * d1 + d2 * d2 + d3 * d3;
    #pragma unroll
    for (int o = 16; o > 0; o >>= 1) s2 += __shfl_xor_sync(0xffffffffu, s2, o);
    __syncthreads();
    if ((tid & 31) == 0) red[tid >> 5] = s2;
    __syncthreads();
    if (tid == 0) {
        float t = 0.f;
        #pragma unroll
        for (int i = 0; i < 8; i++) t += red[i];
        s_rstd = rsqrtf(t * (1.0f / CC) + 1e-5f);
    }
    __syncthreads();
    float rstd = s_rstd;
    __half* orow = out + (size_t)row * CC;
    orow[tid]       = __float2half(d0 * rstd * g[tid]       + b[tid]);
    orow[tid + 256] = __float2half(d1 * rstd * g[tid + 256] + b[tid + 256]);
    orow[tid + 512] = __float2half(d2 * rstd * g[tid + 512] + b[tid + 512]);
    orow[tid + 768] = __float2half(d3 * rstd * g[tid + 768] + b[tid + 768]);
}

// ============================================================
// fp16 GEMM: C = A(MxK) @ Bt^T. A [M][K], Bt [N][K], both fp16.
// BM=BN=128, BK=64 halves, 256 thr = 8 warps (2x4), warp 64x32.
// Tiles 128x128B swizzled; both operand frags via ldmatrix.
// ============================================================
#define GT_BYTES (128 * 128)            // 16KB per tile stage
#define G_SMEM (4 * GT_BYTES)           // 2 stages x (A+B) = 64KB

template <bool RELU, bool HALFOUT>
__global__ __launch_bounds__(256) void gemm_f16(
    const __half* __restrict__ A, const __half* __restrict__ Bt,
    const float* __restrict__ bias, const float* __restrict__ res,
    void* __restrict__ Cout, int M, int N, int K) {
    extern __shared__ char smx[];
    uint32_t sA = (uint32_t)__cvta_generic_to_shared(smx);
    uint32_t sB = sA + 2 * GT_BYTES;

    int tid = threadIdx.x;
    int warp = tid >> 5, lane = tid & 31;
    int g = lane >> 2, t = lane & 3;
    int wm = (warp >> 2) * 64, wn = (warp & 3) * 32;
    int m0 = blockIdx.y * 128, n0 = blockIdx.x * 128;

    float acc[4][4][4] = {};
    int a_row = wm + (lane & 7) + ((lane >> 3) & 1) * 8;
    int a_sg = lane >> 4;
    int b_row = wn + (lane & 7) + (lane >> 4) * 8;
    int b_sg = (lane >> 3) & 1;

    auto pre = [&](int st, int k0) {   // k0 in halves
        #pragma unroll
        for (int i = 0; i < 4; i++) {
            int ch = tid + 256 * i;    // 1024 chunks
            int r = ch >> 3, c = ch & 7;
            cp16(sA + st * GT_BYTES + swz(r, c), A + (size_t)(m0 + r) * K + k0 + c * 8);
        }
        #pragma unroll
        for (int i = 0; i < 4; i++) {
            int ch = tid + 256 * i;
            int r = ch >> 3, c = ch & 7;
            cp16(sB + st * GT_BYTES + swz(r, c), Bt + (size_t)(n0 + r) * K + k0 + c * 8);
        }
        cp_commit();
    };

    pre(0, 0);
    int nk = K >> 6;
    for (int kk = 0; kk < nk; kk++) {
        int st = kk & 1;
        if (kk + 1 < nk) { pre(st ^ 1, (kk + 1) << 6); cp_wait<1>(); }
        else cp_wait<0>();
        __syncthreads();

        uint32_t sAs = sA + st * GT_BYTES;
        uint32_t sBs = sB + st * GT_BYTES;
        #pragma unroll
        for (int ks = 0; ks < 4; ks++) {
            unsigned af[4][4];
            #pragma unroll
            for (int mi = 0; mi < 4; mi++)
                ldsm4(af[mi][0], af[mi][1], af[mi][2], af[mi][3],
                      sAs + swz(a_row + mi * 16, 2 * ks + a_sg));
            #pragma unroll
            for (int nj2 = 0; nj2 < 2; nj2++) {
                unsigned r0, r1, r2, r3;
                ldsm4(r0, r1, r2, r3, sBs + swz(b_row + nj2 * 16, 2 * ks + b_sg));
                unsigned b0[2] = {r0, r1}, b1[2] = {r2, r3};
                #pragma unroll
                for (int mi = 0; mi < 4; mi++) {
                    mma_f16(acc[mi][2 * nj2],     af[mi], b0);
                    mma_f16(acc[mi][2 * nj2 + 1], af[mi], b1);
                }
            }
        }
        __syncthreads();
    }

    #pragma unroll
    for (int mi = 0; mi < 4; mi++) {
        #pragma unroll
        for (int nj = 0; nj < 4; nj++) {
            int c = n0 + wn + nj * 8 + 2 * t;
            int r0 = m0 + wm + mi * 16 + g;
            int r1 = r0 + 8;
            float2 o0 = {acc[mi][nj][0], acc[mi][nj][1]};
            float2 o1 = {acc[mi][nj][2], acc[mi][nj][3]};
            if (bias) {
                float2 bv = *(const float2*)(bias + c);
                o0.x += bv.x; o0.y += bv.y; o1.x += bv.x; o1.y += bv.y;
            }
            if (res) {
                float2 ra = *(const float2*)(res + (size_t)r0 * N + c);
                float2 rb = *(const float2*)(res + (size_t)r1 * N + c);
                o0.x += ra.x; o0.y += ra.y; o1.x += rb.x; o1.y += rb.y;
            }
            if (RELU) {
                o0.x = fmaxf(o0.x, 0.f); o0.y = fmaxf(o0.y, 0.f);
                o1.x = fmaxf(o1.x, 0.f); o1.y = fmaxf(o1.y, 0.f);
            }
            if (HALFOUT) {
                __half* C = (__half*)Cout;
                *(__half2*)(C + (size_t)r0 * N + c) = __floats2half2_rn(o0.x, o0.y);
                *(__half2*)(C + (size_t)r1 * N + c) = __floats2half2_rn(o1.x, o1.y);
            } else {
                float* C = (float*)Cout;
                *(float2*)(C + (size_t)r0 * N + c) = o0;
                *(float2*)(C + (size_t)r1 * N + c) = o1;
            }
        }
    }
}

// ============================================================
// Merged QKV GEMM (fp16): 2 heads per CTA, BN=128.
// A = h1 [M][CC]; Wt [h][DD][CC] -> B rows hp*128 + n.
// Q written scaled x0.125; V written transposed (b,h,d,t).
// ============================================================
__global__ __launch_bounds__(256) void qkv_f16(
    const __half* __restrict__ h, const __half* __restrict__ wqt,
    const __half* __restrict__ wkt, const __half* __restrict__ wvt,
    __half* __restrict__ q, __half* __restrict__ k, __half* __restrict__ v) {
    extern __shared__ char smx[];
    uint32_t sA = (uint32_t)__cvta_generic_to_shared(smx);
    uint32_t sB = sA + 2 * GT_BYTES;

    int which = blockIdx.y >> 3;
    int hp = blockIdx.y & 7;
    const __half* Wt = (which == 0 ? wqt : (which == 1 ? wkt : wvt));
    __half* O = (which == 0 ? q : (which == 1 ? k : v));
    float oscale = (which == 0) ? 0.125f : 1.0f;

    int tid = threadIdx.x;
    int warp = tid >> 5, lane = tid & 31;
    int g = lane >> 2, t = lane & 3;
    int wm = (warp >> 2) * 64, wn = (warp & 3) * 32;
    int m0 = blockIdx.x * 128;

    float acc[4][4][4] = {};
    int a_row = wm + (lane & 7) + ((lane >> 3) & 1) * 8;
    int a_sg = lane >> 4;
    int b_row = wn + (lane & 7) + (lane >> 4) * 8;
    int b_sg = (lane >> 3) & 1;

    auto pre = [&](int st, int k0) {
        #pragma unroll
        for (int i = 0; i < 4; i++) {
            int ch = tid + 256 * i;
            int r = ch >> 3, c = ch & 7;
            cp16(sA + st * GT_BYTES + swz(r, c), h + (size_t)(m0 + r) * CC + k0 + c * 8);
        }
        #pragma unroll
        for (int i = 0; i < 4; i++) {
            int ch = tid + 256 * i;
            int r = ch >> 3, c = ch & 7;
            cp16(sB + st * GT_BYTES + swz(r, c),
                 Wt + (size_t)(hp * 128 + r) * CC + k0 + c * 8);
        }
        cp_commit();
    };

    pre(0, 0);
    int nk = CC >> 6;
    for (int kk = 0; kk < nk; kk++) {
        int st = kk & 1;
        if (kk + 1 < nk) { pre(st ^ 1, (kk + 1) << 6); cp_wait<1>(); }
        else cp_wait<0>();
        __syncthreads();

        uint32_t sAs = sA + st * GT_BYTES;
        uint32_t sBs = sB + st * GT_BYTES;
        #pragma unroll
        for (int ks = 0; ks < 4; ks++) {
            unsigned af[4][4];
            #pragma unroll
            for (int mi = 0; mi < 4; mi++)
                ldsm4(af[mi][0], af[mi][1], af[mi][2], af[mi][3],
                      sAs + swz(a_row + mi * 16, 2 * ks + a_sg));
            #pragma unroll
            for (int nj2 = 0; nj2 < 2; nj2++) {
                unsigned r0, r1, r2, r3;
                ldsm4(r0, r1, r2, r3, sBs + swz(b_row + nj2 * 16, 2 * ks + b_sg));
                unsigned b0[2] = {r0, r1}, b1[2] = {r2, r3};
                #pragma unroll
                for (int mi = 0; mi < 4; mi++) {
                    mma_f16(acc[mi][2 * nj2],     af[mi], b0);
                    mma_f16(acc[mi][2 * nj2 + 1], af[mi], b1);
                }
            }
        }
        __syncthreads();
    }

    #pragma unroll
    for (int mi = 0; mi < 4; mi++) {
        #pragma unroll
        for (int nj = 0; nj < 4; nj++) {
            int c = wn + nj * 8 + 2 * t;
            int head = 2 * hp + (c >> 6);
            int d = c & 63;
            int m0r = m0 + wm + mi * 16 + g;
            int m1r = m0r + 8;
            int b0 = m0r >> 11, t0i = m0r & (TT - 1);
            int b1 = m1r >> 11, t1i = m1r & (TT - 1);
            float a0 = acc[mi][nj][0] * oscale, a1 = acc[mi][nj][1] * oscale;
            float a2 = acc[mi][nj][2] * oscale, a3 = acc[mi][nj][3] * oscale;
            if (which == 2) {
                size_t base0 = ((size_t)(b0 * HH + head) * DD);
                size_t base1 = ((size_t)(b1 * HH + head) * DD);
                O[(base0 + d)     * TT + t0i] = __float2half(a0);
                O[(base0 + d + 1) * TT + t0i] = __float2half(a1);
                O[(base1 + d)     * TT + t1i] = __float2half(a2);
                O[(base1 + d + 1) * TT + t1i] = __float2half(a3);
            } else {
                *(__half2*)(O + (((size_t)(b0 * HH + head) * TT + t0i) << 6) + d) =
                    __floats2half2_rn(a0, a1);
                *(__half2*)(O + (((size_t)(b1 * HH + head) * TT + t1i) << 6) + d) =
                    __floats2half2_rn(a2, a3);
            }
        }
    }
}

// ============================================================
// Flash attention (fp16 operands). Br=64, Bc=64, 128 thr.
// Q/K/V staged via cp.async; P reuses Q buffer (warp-local rows).
// Longest CTAs first. Q pre-scaled. Out fp16.
// ============================================================
__global__ __launch_bounds__(128) void attn_f16(
    const __half* __restrict__ Q, const __half* __restrict__ K,
    const __half* __restrict__ V, __half* __restrict__ out) {
    __shared__ __align__(128) char Qb[64 * 128];   // Q tile, later P tile
    __shared__ __align__(128) char Kb[64 * 128];
    __shared__ __align__(128) char Vb[64 * 128];   // V^T tile [d][s]
    uint32_t sQ = (uint32_t)__cvta_generic_to_shared(Qb);
    uint32_t sK = (uint32_t)__cvta_generic_to_shared(Kb);
    uint32_t sV = (uint32_t)__cvta_generic_to_shared(Vb);

    int bh = blockIdx.y;
    int t0 = (int)(gridDim.x - 1 - blockIdx.x) * 64;
    const __half* Qp = Q + (size_t)bh * TT * DD;
    const __half* Kp = K + (size_t)bh * TT * DD;
    const __half* Vp = V + (size_t)bh * TT * DD;   // (d,t)

    int tid = threadIdx.x;
    int warp = tid >> 5, lane = tid & 31;
    int g = lane >> 2, t = lane & 3;
    int wr = warp * 16;

    int fr_row = (lane & 7) + ((lane >> 3) & 1) * 8;   // A-pattern row
    int fr_sg = lane >> 4;
    int bn_row = (lane & 7) + (lane >> 4) * 8;         // B-pattern row
    int bn_sg = (lane >> 3) & 1;

    // stage Q (already scaled) and pull A-frags
    #pragma unroll
    for (int i = 0; i < 4; i++) {
        int ch = tid + 128 * i;        // 512 chunks
        int r = ch >> 3, c = ch & 7;
        cp16(sQ + swz(r, c), Qp + (size_t)(t0 + r) * DD + c * 8);
    }
    cp_commit();
    cp_wait<0>();
    __syncthreads();
    unsigned qa[4][4];
    #pragma unroll
    for (int ks = 0; ks < 4; ks++)
        ldsm4(qa[ks][0], qa[ks][1], qa[ks][2], qa[ks][3],
              sQ + swz(wr + fr_row, 2 * ks + fr_sg));
    __syncthreads();   // all Q-frag reads done before P overwrites (cross-check cheap)

    float m0r = -1e30f, m1r = -1e30f, l0 = 0.f, l1 = 0.f;
    float oacc[8][4] = {};

    int ntiles = t0 / 64 + 1;
    for (int it = 0; it < ntiles; it++) {
        int s0 = it * 64;
        #pragma unroll
        for (int i = 0; i < 4; i++) {
            int ch = tid + 128 * i;
            int r = ch >> 3, c = ch & 7;
            cp16(sK + swz(r, c), Kp + (size_t)(s0 + r) * DD + c * 8);
        }
        #pragma unroll
        for (int i = 0; i < 4; i++) {
            int ch = tid + 128 * i;
            int d = ch >> 3, c = ch & 7;
            cp16(sV + swz(d, c), Vp + (size_t)d * TT + s0 + c * 8);
        }
        cp_commit();
        cp_wait<0>();
        __syncthreads();

        // S = Q @ K^T (B-frags from Kb, n=key)
        float sacc[8][4] = {};
        #pragma unroll
        for (int ks = 0; ks < 4; ks++) {
            #pragma unroll
            for (int nj2 = 0; nj2 < 4; nj2++) {
                unsigned r0, r1, r2, r3;
                ldsm4(r0, r1, r2, r3, sK + swz(nj2 * 16 + bn_row, 2 * ks + bn_sg));
                unsigned b0[2] = {r0, r1}, b1[2] = {r2, r3};
                mma_f16(sacc[2 * nj2], qa[ks], b0);
                mma_f16(sacc[2 * nj2 + 1], qa[ks], b1);
            }
        }

        // causal mask (diagonal tile only)
        if (s0 == t0) {
            #pragma unroll
            for (int nj = 0; nj < 8; nj++) {
                int c0 = nj * 8 + 2 * t, c1 = c0 + 1;
                int r0 = wr + g, r1 = r0 + 8;
                if (c0 > r0) sacc[nj][0] = -1e30f;
                if (c1 > r0) sacc[nj][1] = -1e30f;
                if (c0 > r1) sacc[nj][2] = -1e30f;
                if (c1 > r1) sacc[nj][3] = -1e30f;
            }
        }

        // online softmax (fp32)
        float mt0 = -1e30f, mt1 = -1e30f;
        #pragma unroll
        for (int nj = 0; nj < 8; nj++) {
            mt0 = fmaxf(mt0, fmaxf(sacc[nj][0], sacc[nj][1]));
            mt1 = fmaxf(mt1, fmaxf(sacc[nj][2], sacc[nj][3]));
        }
        #pragma unroll
        for (int o = 1; o <= 2; o <<= 1) {
            mt0 = fmaxf(mt0, __shfl_xor_sync(0xffffffffu, mt0, o));
            mt1 = fmaxf(mt1, __shfl_xor_sync(0xffffffffu, mt1, o));
        }
        float mn0 = fmaxf(m0r, mt0), mn1 = fmaxf(m1r, mt1);
        float sc0 = __expf(m0r - mn0), sc1 = __expf(m1r - mn1);
        float sum0 = 0.f, sum1 = 0.f;
        int pr0 = wr + g, pr1 = wr + 8 + g;
        #pragma unroll
        for (int nj = 0; nj < 8; nj++) {
            float p00 = __expf(sacc[nj][0] - mn0);
            float p01 = __expf(sacc[nj][1] - mn0);
            float p10 = __expf(sacc[nj][2] - mn1);
            float p11 = __expf(sacc[nj][3] - mn1);
            sum0 += p00 + p01; sum1 += p10 + p11;
            // P into Qb (own warp rows), swizzled half2 store
            *(__half2*)(Qb + pr0 * 128 + ((nj ^ (pr0 & 7)) * 8 + 2 * t) * 2) =
                __floats2half2_rn(p00, p01);
            *(__half2*)(Qb + pr1 * 128 + ((nj ^ (pr1 & 7)) * 8 + 2 * t) * 2) =
                __floats2half2_rn(p10, p11);
        }
        #pragma unroll
        for (int o = 1; o <= 2; o <<= 1) {
            sum0 += __shfl_xor_sync(0xffffffffu, sum0, o);
            sum1 += __shfl_xor_sync(0xffffffffu, sum1, o);
        }
        l0 = l0 * sc0 + sum0;
        l1 = l1 * sc1 + sum1;
        m0r = mn0; m1r = mn1;
        #pragma unroll
        for (int nj = 0; nj < 8; nj++) {
            oacc[nj][0] *= sc0; oacc[nj][1] *= sc0;
            oacc[nj][2] *= sc1; oacc[nj][3] *= sc1;
        }
        __syncwarp();   // P rows are warp-local

        // O += P @ V (P A-frags from Qb, V^T B-frags from Vb, n=d)
        #pragma unroll
        for (int j = 0; j < 4; j++) {          // key segments of 16
            unsigned pa[4];
            ldsm4(pa[0], pa[1], pa[2], pa[3], sQ + swz(wr + fr_row, 2 * j + fr_sg));
            #pragma unroll
            for (int nj2 = 0; nj2 < 4; nj2++) {
                unsigned r0, r1, r2, r3;
                ldsm4(r0, r1, r2, r3, sV + swz(nj2 * 16 + bn_row, 2 * j + bn_sg));
                unsigned b0[2] = {r0, r1}, b1[2] = {r2, r3};
                mma_f16(oacc[2 * nj2], pa, b0);
                mma_f16(oacc[2 * nj2 + 1], pa, b1);
            }
        }
        __syncthreads();   // Kb/Vb consumed before next tile staging
    }

    float inv0 = 1.f / l0, inv1 = 1.f / l1;
    int b = bh >> 4, hh = bh & 15;
    int tr0 = t0 + wr + g, tr1 = tr0 + 8;
    #pragma unroll
    for (int nj = 0; nj < 8; nj++) {
        int c = hh * DD + nj * 8 + 2 * t;
        *(__half2*)(out + (size_t)(b * TT + tr0) * CC + c) =
            __floats2half2_rn(oacc[nj][0] * inv0, oacc[nj][1] * inv0);
        *(__half2*)(out + (size_t)(b * TT + tr1) * CC + c) =
            __floats2half2_rn(oacc[nj][2] * inv1, oacc[nj][3] * inv1);
    }
}

// ============================================================
// launch
// ============================================================
extern "C" void kernel_launch(void* const* d_in, const int* in_sizes, int n_in,
                              void* d_out, int out_size) {
    const float* x      = (const float*)d_in[0];
    const float* wq     = (const float*)d_in[1];
    const float* wk     = (const float*)d_in[2];
    const float* wv     = (const float*)d_in[3];
    const float* w_proj = (const float*)d_in[4];
    const float* b_proj = (const float*)d_in[5];
    const float* w1     = (const float*)d_in[6];
    const float* b1     = (const float*)d_in[7];
    const float* w2     = (const float*)d_in[8];
    const float* b2     = (const float*)d_in[9];
    const float* g1     = (const float*)d_in[10];
    const float* be1    = (const float*)d_in[11];
    const float* g2     = (const float*)d_in[12];
    const float* be2    = (const float*)d_in[13];
    float* out = (float*)d_out;

    __half *h1, *q, *k, *v, *attn, *h2, *ff1;
    __half *wpt, *w1t, *w2t, *wqt, *wkt, *wvt;
    float *x1;
    cudaGetSymbolAddress((void**)&h1, g_h1);
    cudaGetSymbolAddress((void**)&q, g_q);
    cudaGetSymbolAddress((void**)&k, g_k);
    cudaGetSymbolAddress((void**)&v, g_v);
    cudaGetSymbolAddress((void**)&attn, g_attn);
    cudaGetSymbolAddress((void**)&x1, g_x1);
    cudaGetSymbolAddress((void**)&h2, g_h2);
    cudaGetSymbolAddress((void**)&ff1, g_ff1);
    cudaGetSymbolAddress((void**)&wpt, g_wpt);
    cudaGetSymbolAddress((void**)&w1t, g_w1t);
    cudaGetSymbolAddress((void**)&w2t, g_w2t);
    cudaGetSymbolAddress((void**)&wqt, g_wqt);
    cudaGetSymbolAddress((void**)&wkt, g_wkt);
    cudaGetSymbolAddress((void**)&wvt, g_wvt);

    cudaFuncSetAttribute(gemm_f16<false, false>, cudaFuncAttributeMaxDynamicSharedMemorySize, G_SMEM);
    cudaFuncSetAttribute(gemm_f16<true, true>,   cudaFuncAttributeMaxDynamicSharedMemorySize, G_SMEM);
    cudaFuncSetAttribute(qkv_f16, cudaFuncAttributeMaxDynamicSharedMemorySize, G_SMEM);

    // 0. weight transposes -> fp16 [N][K]
    transpose_w<<<dim3(CC / 32, CC / 32, 1), dim3(32, 8)>>>(w_proj, wpt, CC, CC);
    transpose_w<<<dim3(FFDIM / 32, CC / 32, 1), dim3(32, 8)>>>(w1, w1t, CC, FFDIM);
    transpose_w<<<dim3(CC / 32, FFDIM / 32, 1), dim3(32, 8)>>>(w2, w2t, FFDIM, CC);
    transpose_w<<<dim3(DD / 32, CC / 32, HH), dim3(32, 8)>>>(wq, wqt, CC, DD);
    transpose_w<<<dim3(DD / 32, CC / 32, HH), dim3(32, 8)>>>(wk, wkt, CC, DD);
    transpose_w<<<dim3(DD / 32, CC / 32, HH), dim3(32, 8)>>>(wv, wvt, CC, DD);
    // 1. LN1 -> fp16
    ln_kernel<<<MTOT, 256>>>(x, g1, be1, h1);
    // 2. QKV (merged; q pre-scaled, v transposed)
    qkv_f16<<<dim3(MTOT / 128, 3 * (HH / 2)), 256, G_SMEM>>>(h1, wqt, wkt, wvt, q, k, v);
    // 3. attention -> fp16
    attn_f16<<<dim3(TT / 64, BBATCH * HH), 128>>>(q, k, v, attn);
    // 4. proj + bias + residual -> x1 (fp32)
    gemm_f16<false, false><<<dim3(CC / 128, MTOT / 128), 256, G_SMEM>>>(
        attn, wpt, b_proj, x, x1, MTOT, CC, CC);
    // 5. LN2 -> fp16
    ln_kernel<<<MTOT, 256>>>(x1, g2, be2, h2);
    // 6. FF1 + bias + relu -> fp16
    gemm_f16<true, true><<<dim3(FFDIM / 128, MTOT / 128), 256, G_SMEM>>>(
        h2, w1t, b1, nullptr, ff1, MTOT, FFDIM, CC);
    // 7. FF2 + bias + residual -> out (fp32)
    gemm_f16<false, false><<<dim3(CC / 128, MTOT / 128), 256, G_SMEM>>>(
        ff1, w2t, b2, x1, out, MTOT, CC, FFDIM);
}